// round 5
// baseline (speedup 1.0000x reference)
#include <cuda_runtime.h>
#include <math.h>

#define NRAYS 4096
#define NS    256
#define RES   160
#define RES2  (RES*RES)        // 25600
#define RES3  (RES*RES*RES)    // 4096000
#define TNEAR 0.05f
#define TFAR  2.0f
#define ACT_SHIFT (-13.8155095579f)
#define WEPS  1e-9f

// --- trilinear interp helpers ---------------------------------------------
__device__ __forceinline__ void tri_setup(float px, float py, float pz,
                                          int& base, float& fx, float& fy, float& fz)
{
    float ix = fminf(fmaxf((px + 1.0f) * 79.5f, 0.0f), 159.0f);
    float iy = fminf(fmaxf((py + 1.0f) * 79.5f, 0.0f), 159.0f);
    float iz = fminf(fmaxf((pz + 1.0f) * 79.5f, 0.0f), 159.0f);
    int x0 = min((int)ix, 158);
    int y0 = min((int)iy, 158);
    int z0 = min((int)iz, 158);
    fx = ix - (float)x0;
    fy = iy - (float)y0;
    fz = iz - (float)z0;
    base = x0 * RES2 + y0 * RES + z0;
}

__device__ __forceinline__ float tri_fetch(const float* __restrict__ g, int base,
                                           float fx, float fy, float fz)
{
    float c000 = g[base];
    float c001 = g[base + 1];
    float c010 = g[base + RES];
    float c011 = g[base + RES + 1];
    const float* g1 = g + base + RES2;
    float c100 = g1[0];
    float c101 = g1[1];
    float c110 = g1[RES];
    float c111 = g1[RES + 1];
    float gz = 1.0f - fz;
    float c00 = c000 * gz + c001 * fz;
    float c01 = c010 * gz + c011 * fz;
    float c10 = c100 * gz + c101 * fz;
    float c11 = c110 * gz + c111 * fz;
    float gy = 1.0f - fy;
    float c0 = c00 * gy + c01 * fy;
    float c1 = c10 * gy + c11 * fy;
    return c0 * (1.0f - fx) + c1 * fx;
}

// --- main fused kernel: one block (128 threads) per ray --------------------
__global__ __launch_bounds__(128)
void dvgo_kernel(const float* __restrict__ rays_o, const float* __restrict__ rays_d,
                 const float* __restrict__ dens,  const float* __restrict__ feat,
                 const float* __restrict__ w0,    const float* __restrict__ b0,
                 const float* __restrict__ w1,    const float* __restrict__ b1,
                 const float* __restrict__ w2,    const float* __restrict__ b2,
                 float* __restrict__ out)
{
    // s_h is accessed as float4 (LDS.128/STS.128) — MUST be 16B aligned.
    __shared__ __align__(16) float s_h[8 * 128];  // transposed: [neuron k][sample s] => k*8+s
    __shared__ float s_vemb[27];
    __shared__ float s_alpha[NS];
    __shared__ float s_wgt[NS];
    __shared__ float s_x[8 * 12];         // [sample][channel]
    __shared__ float s_rgbw[24];
    __shared__ float s_acc[3];
    __shared__ float s_ainv;

    const int ray = blockIdx.x;
    const int tid = threadIdx.x;

    const float ox = rays_o[ray * 3 + 0];
    const float oy = rays_o[ray * 3 + 1];
    const float oz = rays_o[ray * 3 + 2];
    float rdx = rays_d[ray * 3 + 0];
    float rdy = rays_d[ray * 3 + 1];
    float rdz = rays_d[ray * 3 + 2];
    const float invn = rsqrtf(rdx * rdx + rdy * rdy + rdz * rdz);
    const float vx = rdx * invn, vy = rdy * invn, vz = rdz * invn;

    // view embedding: [v(3), sin(v*2^f) d-major (12), cos (12)]
    if (tid < 27) {
        float val;
        if (tid < 3) {
            val = (tid == 0) ? vx : ((tid == 1) ? vy : vz);
        } else if (tid < 15) {
            int k = tid - 3;
            int d = k >> 2, f = k & 3;
            float v = (d == 0) ? vx : ((d == 1) ? vy : vz);
            val = sinf(v * (float)(1 << f));
        } else {
            int k = tid - 15;
            int d = k >> 2, f = k & 3;
            float v = (d == 0) ? vx : ((d == 1) ? vy : vz);
            val = cosf(v * (float)(1 << f));
        }
        s_vemb[tid] = val;
    }
    if (tid < 3) s_acc[tid] = 0.0f;
    __syncthreads();

    // per-ray constants held in registers (one neuron column per thread)
    float vw = b0[tid];
    #pragma unroll
    for (int k = 0; k < 27; k++) vw += s_vemb[k] * w0[(12 + k) * 128 + tid];

    float wc[12];
    #pragma unroll
    for (int c = 0; c < 12; c++) wc[c] = w0[c * 128 + tid];
    const float b1r = b1[tid];

    // ---- alpha pre-pass --------------------------------------------------
    const float tstep = (TFAR - TNEAR) / 255.0f;
    for (int s = tid; s < NS; s += 128) {
        float t = TNEAR + (float)s * tstep;
        float px = ox + vx * t, py = oy + vy * t, pz = oz + vz * t;
        bool inbox = (px >= -1.0f) & (px <= 1.0f) &
                     (py >= -1.0f) & (py <= 1.0f) &
                     (pz >= -1.0f) & (pz <= 1.0f);
        float alpha = 0.0f;
        if (inbox) {
            int base; float fx, fy, fz;
            tri_setup(px, py, pz, base, fx, fy, fz);
            float d = tri_fetch(dens, base, fx, fy, fz);
            float e = expf(d + ACT_SHIFT);
            alpha = -expm1f(-0.5f * log1pf(e));   // 1 - (1+e)^-0.5, no cancellation
        }
        s_alpha[s] = alpha;
    }
    __syncthreads();

    if (tid == 0) {
        float T = 1.0f;
        for (int s = 0; s < NS; s++) {
            float a = s_alpha[s];
            s_wgt[s] = a * T;
            T *= (1.0f - a);
        }
        s_ainv = T;
    }
    __syncthreads();

    // ---- tiled MLP over samples (8 per tile) -----------------------------
    float4* sh4 = (float4*)s_h;

    for (int tile = 0; tile < 32; tile++) {
        int s0 = tile * 8;
        int any = __syncthreads_or((tid < 8) && (s_wgt[s0 + tid] > WEPS));
        if (!any) continue;

        // feature trilerp: 96 threads, (sample, channel)
        if (tid < 96) {
            int ss = tid / 12;
            int c  = tid - ss * 12;
            float t = TNEAR + (float)(s0 + ss) * tstep;
            float px = ox + vx * t, py = oy + vy * t, pz = oz + vz * t;
            int base; float fx, fy, fz;
            tri_setup(px, py, pz, base, fx, fy, fz);
            s_x[ss * 12 + c] = tri_fetch(feat + c * RES3, base, fx, fy, fz);
        }
        __syncthreads();

        // layer 0 (feature part; view part pre-folded into vw)
        float h[8];
        #pragma unroll
        for (int s = 0; s < 8; s++) h[s] = vw;
        #pragma unroll
        for (int c = 0; c < 12; c++) {
            float w = wc[c];
            #pragma unroll
            for (int s = 0; s < 8; s++) h[s] += s_x[s * 12 + c] * w;
        }
        #pragma unroll
        for (int s = 0; s < 8; s++) h[s] = fmaxf(h[s], 0.0f);

        sh4[tid * 2 + 0] = make_float4(h[0], h[1], h[2], h[3]);
        sh4[tid * 2 + 1] = make_float4(h[4], h[5], h[6], h[7]);
        __syncthreads();

        // layer 1: 128x128, register-tiled over 8 samples
        float g[8];
        #pragma unroll
        for (int s = 0; s < 8; s++) g[s] = b1r;
        #pragma unroll 4
        for (int k = 0; k < 128; k++) {
            float w = w1[k * 128 + tid];
            float4 a = sh4[k * 2 + 0];
            float4 b = sh4[k * 2 + 1];
            g[0] += a.x * w; g[1] += a.y * w; g[2] += a.z * w; g[3] += a.w * w;
            g[4] += b.x * w; g[5] += b.y * w; g[6] += b.z * w; g[7] += b.w * w;
        }
        __syncthreads();   // done reading h0 before overwrite
        sh4[tid * 2 + 0] = make_float4(fmaxf(g[0], 0.0f), fmaxf(g[1], 0.0f),
                                       fmaxf(g[2], 0.0f), fmaxf(g[3], 0.0f));
        sh4[tid * 2 + 1] = make_float4(fmaxf(g[4], 0.0f), fmaxf(g[5], 0.0f),
                                       fmaxf(g[6], 0.0f), fmaxf(g[7], 0.0f));
        __syncthreads();

        // layer 2 + sigmoid + weighted accumulate
        if (tid < 24) {
            int ss = tid / 3;
            int c  = tid - ss * 3;
            float a = b2[c];
            #pragma unroll 8
            for (int k = 0; k < 128; k++) a += s_h[k * 8 + ss] * w2[k * 3 + c];
            float r = 1.0f / (1.0f + expf(-a));
            s_rgbw[tid] = s_wgt[s0 + ss] * r;
        }
        __syncthreads();
        if (tid < 3) {
            float a = 0.0f;
            #pragma unroll
            for (int ss = 0; ss < 8; ss++) a += s_rgbw[ss * 3 + tid];
            s_acc[tid] += a;
        }
        // loop-top __syncthreads_or provides the barrier before reuse
    }

    __syncthreads();
    if (tid < 3) out[ray * 3 + tid] = s_acc[tid] + s_ainv;
}

extern "C" void kernel_launch(void* const* d_in, const int* in_sizes, int n_in,
                              void* d_out, int out_size)
{
    const float* rays_o = (const float*)d_in[0];
    const float* rays_d = (const float*)d_in[1];
    const float* dens   = (const float*)d_in[2];
    const float* feat   = (const float*)d_in[3];
    const float* w0     = (const float*)d_in[4];
    const float* b0     = (const float*)d_in[5];
    const float* w1     = (const float*)d_in[6];
    const float* b1     = (const float*)d_in[7];
    const float* w2     = (const float*)d_in[8];
    const float* b2     = (const float*)d_in[9];
    float* out = (float*)d_out;

    dvgo_kernel<<<NRAYS, 128>>>(rays_o, rays_d, dens, feat,
                                w0, b0, w1, b1, w2, b2, out);
}

// round 7
// speedup vs baseline: 3.2887x; 3.2887x over previous
#include <cuda_runtime.h>
#include <cuda_bf16.h>
#include <math.h>

#define NRAYS 4096
#define NS    256
#define RES   160
#define RES2  (RES*RES)
#define RES3  (RES*RES*RES)
#define TNEAR 0.05f
#define TFAR  2.0f
#define ACT_SHIFT (-13.8155095579f)
#define WEPS  1e-9f

// packed bf16x2 weight fragments: [n][kpair], low half = even k
__device__ unsigned int g_w0p[128 * 8];    // layer0: k 0..15 (12 real, 4 zero)
__device__ unsigned int g_w1p[128 * 64];   // layer1: k 0..127
__device__ unsigned int g_w2p[8 * 64];     // layer2: n 0..7 (3 real, 5 zero)

__device__ __forceinline__ unsigned int packbf2(float lo, float hi) {
    __nv_bfloat162 h = __floats2bfloat162_rn(lo, hi);
    return *reinterpret_cast<unsigned int*>(&h);
}

__global__ void prep_kernel(const float* __restrict__ w0,
                            const float* __restrict__ w1,
                            const float* __restrict__ w2)
{
    int i = blockIdx.x * 256 + threadIdx.x;
    if (i < 128 * 64) {            // w1p: n = i>>6, p = i&63
        int n = i >> 6, p = i & 63;
        g_w1p[i] = packbf2(w1[(2 * p) * 128 + n], w1[(2 * p + 1) * 128 + n]);
    }
    if (i < 128 * 8) {             // w0p: n = i>>3, p = i&7  (k = 2p, 2p+1; zero for k>=12)
        int n = i >> 3, p = i & 7;
        int k0 = 2 * p, k1 = 2 * p + 1;
        float lo = (k0 < 12) ? w0[k0 * 128 + n] : 0.0f;
        float hi = (k1 < 12) ? w0[k1 * 128 + n] : 0.0f;
        g_w0p[i] = packbf2(lo, hi);
    }
    if (i < 8 * 64) {              // w2p: n = i>>6, p = i&63 (zero for n>=3)
        int n = i >> 6, p = i & 63;
        float lo = (n < 3) ? w2[(2 * p) * 3 + n] : 0.0f;
        float hi = (n < 3) ? w2[(2 * p + 1) * 3 + n] : 0.0f;
        g_w2p[i] = packbf2(lo, hi);
    }
}

#define LDSM4(A0,A1,A2,A3,addr) \
    asm volatile("ldmatrix.sync.aligned.m8n8.x4.shared.b16 {%0,%1,%2,%3}, [%4];" \
        : "=r"(A0), "=r"(A1), "=r"(A2), "=r"(A3) : "r"(addr))

#define MMA_BF16(C,A0,A1,A2,A3,B0r,B1r) \
    asm volatile("mma.sync.aligned.m16n8k16.row.col.f32.bf16.bf16.f32 " \
        "{%0,%1,%2,%3}, {%4,%5,%6,%7}, {%8,%9}, {%0,%1,%2,%3};" \
        : "+f"((C)[0]), "+f"((C)[1]), "+f"((C)[2]), "+f"((C)[3]) \
        : "r"(A0), "r"(A1), "r"(A2), "r"(A3), "r"(B0r), "r"(B1r))

// --- trilinear interp helpers ---------------------------------------------
__device__ __forceinline__ void tri_setup(float px, float py, float pz,
                                          int& base, float& fx, float& fy, float& fz)
{
    float ix = fminf(fmaxf((px + 1.0f) * 79.5f, 0.0f), 159.0f);
    float iy = fminf(fmaxf((py + 1.0f) * 79.5f, 0.0f), 159.0f);
    float iz = fminf(fmaxf((pz + 1.0f) * 79.5f, 0.0f), 159.0f);
    int x0 = min((int)ix, 158);
    int y0 = min((int)iy, 158);
    int z0 = min((int)iz, 158);
    fx = ix - (float)x0;
    fy = iy - (float)y0;
    fz = iz - (float)z0;
    base = x0 * RES2 + y0 * RES + z0;
}

__device__ __forceinline__ float tri_fetch(const float* __restrict__ g, int base,
                                           float fx, float fy, float fz)
{
    float c000 = g[base];
    float c001 = g[base + 1];
    float c010 = g[base + RES];
    float c011 = g[base + RES + 1];
    const float* g1 = g + base + RES2;
    float c100 = g1[0];
    float c101 = g1[1];
    float c110 = g1[RES];
    float c111 = g1[RES + 1];
    float gz = 1.0f - fz;
    float c00 = c000 * gz + c001 * fz;
    float c01 = c010 * gz + c011 * fz;
    float c10 = c100 * gz + c101 * fz;
    float c11 = c110 * gz + c111 * fz;
    float gy = 1.0f - fy;
    float c0 = c00 * gy + c01 * fy;
    float c1 = c10 * gy + c11 * fy;
    return c0 * (1.0f - fx) + c1 * fx;
}

__device__ __forceinline__ float sigm(float x) { return 1.0f / (1.0f + expf(-x)); }

// --- main fused kernel: one block (128 threads) per ray --------------------
// 16-sample tiles; MLP on tensor pipe (bf16 mma.sync, fp32 accum).
// smem A layouts: s_xb [16 samples][24 bf16] (stride 48B, 12 real + 4 zero-pad k)
//                 s_h  [16 samples][136 bf16] (stride 272B, 128 real)
__global__ __launch_bounds__(128)
void dvgo_kernel(const float* __restrict__ rays_o, const float* __restrict__ rays_d,
                 const float* __restrict__ dens,  const float* __restrict__ feat,
                 const float* __restrict__ w0,    const float* __restrict__ b0,
                 const float* __restrict__ w1,    const float* __restrict__ b1,
                 const float* __restrict__ w2,    const float* __restrict__ b2,
                 float* __restrict__ out)
{
    __shared__ __align__(16) __nv_bfloat16 s_h[16 * 136];
    __shared__ __align__(16) __nv_bfloat16 s_xb[16 * 24];
    __shared__ float s_vw[128];
    __shared__ float s_vemb[27];
    __shared__ float s_alpha[NS];
    __shared__ float s_wgt[NS];
    __shared__ float s_acc[3];
    __shared__ float s_ainv;

    const int ray = blockIdx.x;
    const int tid = threadIdx.x;
    const int wid = tid >> 5;
    const int lane = tid & 31;
    const int gq = lane >> 2;        // group id 0..7
    const int tq = lane & 3;         // thread-in-group 0..3

    const float ox = rays_o[ray * 3 + 0];
    const float oy = rays_o[ray * 3 + 1];
    const float oz = rays_o[ray * 3 + 2];
    float rdx = rays_d[ray * 3 + 0];
    float rdy = rays_d[ray * 3 + 1];
    float rdz = rays_d[ray * 3 + 2];
    const float invn = rsqrtf(rdx * rdx + rdy * rdy + rdz * rdz);
    const float vx = rdx * invn, vy = rdy * invn, vz = rdz * invn;

    // view embedding
    if (tid < 27) {
        float val;
        if (tid < 3) {
            val = (tid == 0) ? vx : ((tid == 1) ? vy : vz);
        } else if (tid < 15) {
            int k = tid - 3;
            int d = k >> 2, f = k & 3;
            float v = (d == 0) ? vx : ((d == 1) ? vy : vz);
            val = sinf(v * (float)(1 << f));
        } else {
            int k = tid - 15;
            int d = k >> 2, f = k & 3;
            float v = (d == 0) ? vx : ((d == 1) ? vy : vz);
            val = cosf(v * (float)(1 << f));
        }
        s_vemb[tid] = val;
    }
    if (tid < 3) s_acc[tid] = 0.0f;
    __syncthreads();

    // fold view embedding through w0 (fp32): vw[n] per neuron, n = tid
    {
        float vw = b0[tid];
        #pragma unroll
        for (int k = 0; k < 27; k++) vw += s_vemb[k] * w0[(12 + k) * 128 + tid];
        s_vw[tid] = vw;
    }

    // ---- alpha pre-pass --------------------------------------------------
    const float tstep = (TFAR - TNEAR) / 255.0f;
    for (int s = tid; s < NS; s += 128) {
        float t = TNEAR + (float)s * tstep;
        float px = ox + vx * t, py = oy + vy * t, pz = oz + vz * t;
        bool inbox = (px >= -1.0f) & (px <= 1.0f) &
                     (py >= -1.0f) & (py <= 1.0f) &
                     (pz >= -1.0f) & (pz <= 1.0f);
        float alpha = 0.0f;
        if (inbox) {
            int base; float fx, fy, fz;
            tri_setup(px, py, pz, base, fx, fy, fz);
            float d = tri_fetch(dens, base, fx, fy, fz);
            float e = expf(d + ACT_SHIFT);
            alpha = -expm1f(-0.5f * log1pf(e));
        }
        s_alpha[s] = alpha;
    }
    __syncthreads();

    if (tid == 0) {
        float T = 1.0f;
        for (int s = 0; s < NS; s++) {
            float a = s_alpha[s];
            s_wgt[s] = a * T;
            T *= (1.0f - a);
        }
        s_ainv = T;
    }

    // ---- load resident B fragments (w0, w1) ------------------------------
    const int nbase = wid * 32;
    unsigned int B1[4][8][2];
    unsigned int B0f[4][2];
    #pragma unroll
    for (int nt = 0; nt < 4; nt++) {
        int n = nbase + nt * 8 + gq;
        #pragma unroll
        for (int ks = 0; ks < 8; ks++) {
            B1[nt][ks][0] = g_w1p[n * 64 + ks * 8 + tq];
            B1[nt][ks][1] = g_w1p[n * 64 + ks * 8 + 4 + tq];
        }
        B0f[nt][0] = g_w0p[n * 8 + tq];
        B0f[nt][1] = g_w0p[n * 8 + 4 + tq];
    }
    float b1lo[4], b1hi[4];
    #pragma unroll
    for (int nt = 0; nt < 4; nt++) {
        int c0 = nbase + nt * 8 + 2 * tq;
        b1lo[nt] = b1[c0];
        b1hi[nt] = b1[c0 + 1];
    }
    const float bias2 = (2 * tq < 3) ? b2[2 * tq] : 0.0f;
    const float bias2b = (2 * tq + 1 < 3) ? b2[2 * tq + 1] : 0.0f;

    // ldmatrix per-lane addresses
    const unsigned int xb_base = (unsigned int)__cvta_generic_to_shared(s_xb);
    const unsigned int h_base  = (unsigned int)__cvta_generic_to_shared(s_h);
    const int lrow = (((lane >> 3) & 1) << 3) + (lane & 7);  // matrix row 0..15
    const int lch  = (lane >> 4) & 1;                         // k-half (0/1)
    const unsigned int xaddr = xb_base + lrow * 48 + lch * 16;
    const unsigned int haddr0 = h_base + lrow * 272 + lch * 16;

    // epilogue accumulators (warp0 lanes; col identity fixed per lane)
    float racc0 = 0.0f, racc1 = 0.0f, racc2 = 0.0f, racc3 = 0.0f;

    __syncthreads();

    // ---- 16 tiles x 16 samples -------------------------------------------
    for (int tile = 0; tile < 16; tile++) {
        int s0 = tile * 16;
        int any = __syncthreads_or((tid < 16) && (s_wgt[s0 + tid] > WEPS));
        if (!any) continue;

        // zero-pad k=12..15
        if (tid < 64) {
            int ss = tid >> 2, c = 12 + (tid & 3);
            s_xb[ss * 24 + c] = __float2bfloat16(0.0f);
        }
        // gather: 192 items (16 samples x 12 channels)
        for (int it = tid; it < 192; it += 128) {
            int ss = it / 12;
            int c  = it - ss * 12;
            float t = TNEAR + (float)(s0 + ss) * tstep;
            float px = ox + vx * t, py = oy + vy * t, pz = oz + vz * t;
            int base; float fx, fy, fz;
            tri_setup(px, py, pz, base, fx, fy, fz);
            float v = tri_fetch(feat + c * RES3, base, fx, fy, fz);
            s_xb[ss * 24 + c] = __float2bfloat16(v);
        }
        __syncthreads();

        // ---- layer 0: [16x16] x [16x128] ----
        unsigned int a0, a1, a2, a3;
        LDSM4(a0, a1, a2, a3, xaddr);
        float C0[4][4];
        #pragma unroll
        for (int nt = 0; nt < 4; nt++) {
            C0[nt][0] = 0.0f; C0[nt][1] = 0.0f; C0[nt][2] = 0.0f; C0[nt][3] = 0.0f;
            MMA_BF16(C0[nt], a0, a1, a2, a3, B0f[nt][0], B0f[nt][1]);
        }
        // add vw, relu, store h0 (bf16) to s_h
        #pragma unroll
        for (int nt = 0; nt < 4; nt++) {
            int cc = nbase + nt * 8 + 2 * tq;
            float v0 = s_vw[cc], v1 = s_vw[cc + 1];
            unsigned int wlo = packbf2(fmaxf(C0[nt][0] + v0, 0.0f),
                                       fmaxf(C0[nt][1] + v1, 0.0f));
            unsigned int whi = packbf2(fmaxf(C0[nt][2] + v0, 0.0f),
                                       fmaxf(C0[nt][3] + v1, 0.0f));
            *reinterpret_cast<unsigned int*>(&s_h[gq * 136 + cc]) = wlo;
            *reinterpret_cast<unsigned int*>(&s_h[(gq + 8) * 136 + cc]) = whi;
        }
        __syncthreads();

        // ---- layer 1: [16x128] x [128x128] ----
        float C1[4][4];
        #pragma unroll
        for (int nt = 0; nt < 4; nt++) {
            C1[nt][0] = b1lo[nt]; C1[nt][1] = b1hi[nt];
            C1[nt][2] = b1lo[nt]; C1[nt][3] = b1hi[nt];
        }
        #pragma unroll
        for (int ks = 0; ks < 8; ks++) {
            unsigned int h0, h1, h2, h3;
            LDSM4(h0, h1, h2, h3, haddr0 + ks * 32);
            #pragma unroll
            for (int nt = 0; nt < 4; nt++)
                MMA_BF16(C1[nt], h0, h1, h2, h3, B1[nt][ks][0], B1[nt][ks][1]);
        }
        __syncthreads();   // everyone done reading h0
        #pragma unroll
        for (int nt = 0; nt < 4; nt++) {
            int cc = nbase + nt * 8 + 2 * tq;
            unsigned int wlo = packbf2(fmaxf(C1[nt][0], 0.0f), fmaxf(C1[nt][1], 0.0f));
            unsigned int whi = packbf2(fmaxf(C1[nt][2], 0.0f), fmaxf(C1[nt][3], 0.0f));
            *reinterpret_cast<unsigned int*>(&s_h[gq * 136 + cc]) = wlo;
            *reinterpret_cast<unsigned int*>(&s_h[(gq + 8) * 136 + cc]) = whi;
        }
        __syncthreads();

        // ---- layer 2 (warp 0 only): [16x128] x [128x8(3 real)] + epilogue
        if (wid == 0) {
            float C2[4] = {bias2, bias2b, bias2, bias2b};
            #pragma unroll
            for (int ks = 0; ks < 8; ks++) {
                unsigned int h0, h1, h2, h3;
                LDSM4(h0, h1, h2, h3, haddr0 + ks * 32);
                unsigned int wb0 = g_w2p[gq * 64 + ks * 8 + tq];
                unsigned int wb1 = g_w2p[gq * 64 + ks * 8 + 4 + tq];
                MMA_BF16(C2, h0, h1, h2, h3, wb0, wb1);
            }
            float wlo = s_wgt[s0 + gq];
            float whi = s_wgt[s0 + 8 + gq];
            int col0 = 2 * tq;
            if (col0 < 3) {
                racc0 += wlo * sigm(C2[0]);
                racc2 += whi * sigm(C2[2]);
            }
            if (col0 + 1 < 3) {
                racc1 += wlo * sigm(C2[1]);
                racc3 += whi * sigm(C2[3]);
            }
        }
        // next-tile loop-top __syncthreads_or orders warp0's s_h reads
        // before the next layer-0 overwrite.
    }

    // fold per-lane accumulators into s_acc
    if (wid == 0) {
        int col0 = 2 * tq;
        if (col0 < 3)     atomicAdd(&s_acc[col0],     racc0 + racc2);
        if (col0 + 1 < 3) atomicAdd(&s_acc[col0 + 1], racc1 + racc3);
    }
    __syncthreads();
    if (tid < 3) out[ray * 3 + tid] = s_acc[tid] + s_ainv;
}

extern "C" void kernel_launch(void* const* d_in, const int* in_sizes, int n_in,
                              void* d_out, int out_size)
{
    const float* rays_o = (const float*)d_in[0];
    const float* rays_d = (const float*)d_in[1];
    const float* dens   = (const float*)d_in[2];
    const float* feat   = (const float*)d_in[3];
    const float* w0     = (const float*)d_in[4];
    const float* b0     = (const float*)d_in[5];
    const float* w1     = (const float*)d_in[6];
    const float* b1     = (const float*)d_in[7];
    const float* w2     = (const float*)d_in[8];
    const float* b2     = (const float*)d_in[9];
    float* out = (float*)d_out;

    prep_kernel<<<32, 256>>>(w0, w1, w2);
    dvgo_kernel<<<NRAYS, 128>>>(rays_o, rays_d, dens, feat,
                                w0, b0, w1, b1, w2, b2, out);
}

// round 8
// speedup vs baseline: 3.7039x; 1.1262x over previous
#include <cuda_runtime.h>
#include <cuda_bf16.h>
#include <math.h>

#define NRAYS 4096
#define NS    256
#define RES   160
#define RES2  (RES*RES)
#define RES3  (RES*RES*RES)
#define TNEAR 0.05f
#define TFAR  2.0f
#define ACT_SHIFT (-13.8155095579f)
#define WEPS  1e-9f

// packed bf16x2 weight fragments: [n][kpair], low half = even k
__device__ unsigned int g_w0p[128 * 8];    // layer0: k 0..15 (12 real, 4 zero)
__device__ unsigned int g_w1p[128 * 64];   // layer1: k 0..127
__device__ unsigned int g_w2p[8 * 64];     // layer2: n 0..7 (3 real, 5 zero)

// channel-interleaved feature grid: 32B record per voxel = 12 bf16 + 4 pad
// (8 u32 words). One trilerp corner = one 32B sector = 2x LDG.128.
__device__ __align__(16) unsigned int g_pack[RES3 * 8];   // 131 MB static

__device__ __forceinline__ unsigned int packbf2(float lo, float hi) {
    __nv_bfloat162 h = __floats2bfloat162_rn(lo, hi);
    return *reinterpret_cast<unsigned int*>(&h);
}

__global__ void prep_kernel(const float* __restrict__ w0,
                            const float* __restrict__ w1,
                            const float* __restrict__ w2)
{
    int i = blockIdx.x * 256 + threadIdx.x;
    if (i < 128 * 64) {            // w1p: n = i>>6, p = i&63
        int n = i >> 6, p = i & 63;
        g_w1p[i] = packbf2(w1[(2 * p) * 128 + n], w1[(2 * p + 1) * 128 + n]);
    }
    if (i < 128 * 8) {             // w0p: n = i>>3, p = i&7
        int n = i >> 3, p = i & 7;
        int k0 = 2 * p, k1 = 2 * p + 1;
        float lo = (k0 < 12) ? w0[k0 * 128 + n] : 0.0f;
        float hi = (k1 < 12) ? w0[k1 * 128 + n] : 0.0f;
        g_w0p[i] = packbf2(lo, hi);
    }
    if (i < 8 * 64) {              // w2p: n = i>>6, p = i&63
        int n = i >> 6, p = i & 63;
        float lo = (n < 3) ? w2[(2 * p) * 3 + n] : 0.0f;
        float hi = (n < 3) ? w2[(2 * p + 1) * 3 + n] : 0.0f;
        g_w2p[i] = packbf2(lo, hi);
    }
}

// transpose [12][RES3] fp32 -> [RES3][12] bf16 (+pad). Reads coalesced per
// channel, writes 32B/thread fully coalesced.
__global__ void relayout_kernel(const float* __restrict__ feat)
{
    int v = blockIdx.x * 256 + threadIdx.x;
    if (v >= RES3) return;
    unsigned int r[8];
    #pragma unroll
    for (int p = 0; p < 6; p++)
        r[p] = packbf2(feat[(2 * p) * RES3 + v], feat[(2 * p + 1) * RES3 + v]);
    r[6] = 0u; r[7] = 0u;
    uint4* dst = reinterpret_cast<uint4*>(g_pack) + (size_t)v * 2;
    dst[0] = make_uint4(r[0], r[1], r[2], r[3]);
    dst[1] = make_uint4(r[4], r[5], r[6], r[7]);
}

#define LDSM4(A0,A1,A2,A3,addr) \
    asm volatile("ldmatrix.sync.aligned.m8n8.x4.shared.b16 {%0,%1,%2,%3}, [%4];" \
        : "=r"(A0), "=r"(A1), "=r"(A2), "=r"(A3) : "r"(addr))

#define MMA_BF16(C,A0,A1,A2,A3,B0r,B1r) \
    asm volatile("mma.sync.aligned.m16n8k16.row.col.f32.bf16.bf16.f32 " \
        "{%0,%1,%2,%3}, {%4,%5,%6,%7}, {%8,%9}, {%0,%1,%2,%3};" \
        : "+f"((C)[0]), "+f"((C)[1]), "+f"((C)[2]), "+f"((C)[3]) \
        : "r"(A0), "r"(A1), "r"(A2), "r"(A3), "r"(B0r), "r"(B1r))

// --- trilinear interp helpers ---------------------------------------------
__device__ __forceinline__ void tri_setup(float px, float py, float pz,
                                          int& base, float& fx, float& fy, float& fz)
{
    float ix = fminf(fmaxf((px + 1.0f) * 79.5f, 0.0f), 159.0f);
    float iy = fminf(fmaxf((py + 1.0f) * 79.5f, 0.0f), 159.0f);
    float iz = fminf(fmaxf((pz + 1.0f) * 79.5f, 0.0f), 159.0f);
    int x0 = min((int)ix, 158);
    int y0 = min((int)iy, 158);
    int z0 = min((int)iz, 158);
    fx = ix - (float)x0;
    fy = iy - (float)y0;
    fz = iz - (float)z0;
    base = x0 * RES2 + y0 * RES + z0;
}

__device__ __forceinline__ float tri_fetch(const float* __restrict__ g, int base,
                                           float fx, float fy, float fz)
{
    float c000 = g[base];
    float c001 = g[base + 1];
    float c010 = g[base + RES];
    float c011 = g[base + RES + 1];
    const float* g1 = g + base + RES2;
    float c100 = g1[0];
    float c101 = g1[1];
    float c110 = g1[RES];
    float c111 = g1[RES + 1];
    float gz = 1.0f - fz;
    float c00 = c000 * gz + c001 * fz;
    float c01 = c010 * gz + c011 * fz;
    float c10 = c100 * gz + c101 * fz;
    float c11 = c110 * gz + c111 * fz;
    float gy = 1.0f - fy;
    float c0 = c00 * gy + c01 * fy;
    float c1 = c10 * gy + c11 * fy;
    return c0 * (1.0f - fx) + c1 * fx;
}

__device__ __forceinline__ float sigm(float x) { return 1.0f / (1.0f + expf(-x)); }

// --- main fused kernel: one block (128 threads) per ray --------------------
__global__ __launch_bounds__(128)
void dvgo_kernel(const float* __restrict__ rays_o, const float* __restrict__ rays_d,
                 const float* __restrict__ dens,  const float* __restrict__ feat,
                 const float* __restrict__ w0,    const float* __restrict__ b0,
                 const float* __restrict__ w1,    const float* __restrict__ b1,
                 const float* __restrict__ w2,    const float* __restrict__ b2,
                 float* __restrict__ out)
{
    __shared__ __align__(16) __nv_bfloat16 s_h[16 * 136];
    __shared__ __align__(16) __nv_bfloat16 s_xb[16 * 24];
    __shared__ float s_vw[128];
    __shared__ float s_vemb[27];
    __shared__ float s_alpha[NS];
    __shared__ float s_wgt[NS];
    __shared__ float s_acc[3];
    __shared__ float s_ainv;

    const int ray = blockIdx.x;
    const int tid = threadIdx.x;
    const int wid = tid >> 5;
    const int lane = tid & 31;
    const int gq = lane >> 2;        // group id 0..7
    const int tq = lane & 3;         // thread-in-group 0..3

    const float ox = rays_o[ray * 3 + 0];
    const float oy = rays_o[ray * 3 + 1];
    const float oz = rays_o[ray * 3 + 2];
    float rdx = rays_d[ray * 3 + 0];
    float rdy = rays_d[ray * 3 + 1];
    float rdz = rays_d[ray * 3 + 2];
    const float invn = rsqrtf(rdx * rdx + rdy * rdy + rdz * rdz);
    const float vx = rdx * invn, vy = rdy * invn, vz = rdz * invn;

    // view embedding
    if (tid < 27) {
        float val;
        if (tid < 3) {
            val = (tid == 0) ? vx : ((tid == 1) ? vy : vz);
        } else if (tid < 15) {
            int k = tid - 3;
            int d = k >> 2, f = k & 3;
            float v = (d == 0) ? vx : ((d == 1) ? vy : vz);
            val = sinf(v * (float)(1 << f));
        } else {
            int k = tid - 15;
            int d = k >> 2, f = k & 3;
            float v = (d == 0) ? vx : ((d == 1) ? vy : vz);
            val = cosf(v * (float)(1 << f));
        }
        s_vemb[tid] = val;
    }
    if (tid < 3) s_acc[tid] = 0.0f;
    __syncthreads();

    // fold view embedding through w0 (fp32): vw[n] per neuron, n = tid
    {
        float vw = b0[tid];
        #pragma unroll
        for (int k = 0; k < 27; k++) vw += s_vemb[k] * w0[(12 + k) * 128 + tid];
        s_vw[tid] = vw;
    }

    // ---- alpha pre-pass --------------------------------------------------
    const float tstep = (TFAR - TNEAR) / 255.0f;
    for (int s = tid; s < NS; s += 128) {
        float t = TNEAR + (float)s * tstep;
        float px = ox + vx * t, py = oy + vy * t, pz = oz + vz * t;
        bool inbox = (px >= -1.0f) & (px <= 1.0f) &
                     (py >= -1.0f) & (py <= 1.0f) &
                     (pz >= -1.0f) & (pz <= 1.0f);
        float alpha = 0.0f;
        if (inbox) {
            int base; float fx, fy, fz;
            tri_setup(px, py, pz, base, fx, fy, fz);
            float d = tri_fetch(dens, base, fx, fy, fz);
            float e = expf(d + ACT_SHIFT);
            alpha = -expm1f(-0.5f * log1pf(e));
        }
        s_alpha[s] = alpha;
    }
    __syncthreads();

    if (tid == 0) {
        float T = 1.0f;
        for (int s = 0; s < NS; s++) {
            float a = s_alpha[s];
            s_wgt[s] = a * T;
            T *= (1.0f - a);
        }
        s_ainv = T;
    }

    // ---- load resident B fragments (w0, w1) ------------------------------
    const int nbase = wid * 32;
    unsigned int B1[4][8][2];
    unsigned int B0f[4][2];
    #pragma unroll
    for (int nt = 0; nt < 4; nt++) {
        int n = nbase + nt * 8 + gq;
        #pragma unroll
        for (int ks = 0; ks < 8; ks++) {
            B1[nt][ks][0] = g_w1p[n * 64 + ks * 8 + tq];
            B1[nt][ks][1] = g_w1p[n * 64 + ks * 8 + 4 + tq];
        }
        B0f[nt][0] = g_w0p[n * 8 + tq];
        B0f[nt][1] = g_w0p[n * 8 + 4 + tq];
    }
    float b1lo[4], b1hi[4];
    #pragma unroll
    for (int nt = 0; nt < 4; nt++) {
        int c0 = nbase + nt * 8 + 2 * tq;
        b1lo[nt] = b1[c0];
        b1hi[nt] = b1[c0 + 1];
    }
    const float bias2 = (2 * tq < 3) ? b2[2 * tq] : 0.0f;
    const float bias2b = (2 * tq + 1 < 3) ? b2[2 * tq + 1] : 0.0f;

    // ldmatrix per-lane addresses
    const unsigned int xb_base = (unsigned int)__cvta_generic_to_shared(s_xb);
    const unsigned int h_base  = (unsigned int)__cvta_generic_to_shared(s_h);
    const int lrow = (((lane >> 3) & 1) << 3) + (lane & 7);  // matrix row 0..15
    const int lch  = (lane >> 4) & 1;                         // k-half (0/1)
    const unsigned int xaddr = xb_base + lrow * 48 + lch * 16;
    const unsigned int haddr0 = h_base + lrow * 272 + lch * 16;

    // gather identity: 8 threads per sample, one corner each
    const int g_ss = tid >> 3;           // sample in tile 0..15
    const int g_c3 = tid & 7;
    const int g_dz = g_c3 & 1;
    const int g_dy = (g_c3 >> 1) & 1;
    const int g_dx = (g_c3 >> 2) & 1;

    // epilogue accumulators (warp0 lanes; col identity fixed per lane)
    float racc0 = 0.0f, racc1 = 0.0f, racc2 = 0.0f, racc3 = 0.0f;

    __syncthreads();

    // ---- 16 tiles x 16 samples -------------------------------------------
    for (int tile = 0; tile < 16; tile++) {
        int s0 = tile * 16;
        int any = __syncthreads_or((tid < 16) && (s_wgt[s0 + tid] > WEPS));
        if (!any) continue;

        // gather: one 32B voxel record per corner (2x LDG.128), weighted
        // shfl-butterfly reduce over the 8 corner lanes.
        {
            float t = TNEAR + (float)(s0 + g_ss) * tstep;
            float px = ox + vx * t, py = oy + vy * t, pz = oz + vz * t;
            int base; float fx, fy, fz;
            tri_setup(px, py, pz, base, fx, fy, fz);
            float w = (g_dx ? fx : 1.0f - fx) *
                      (g_dy ? fy : 1.0f - fy) *
                      (g_dz ? fz : 1.0f - fz);
            const uint4* rec = reinterpret_cast<const uint4*>(g_pack) +
                (size_t)(base + g_dx * RES2 + g_dy * RES + g_dz) * 2;
            uint4 ra = rec[0];
            uint4 rb = rec[1];
            float f[12];
            {
                unsigned int wds[6] = {ra.x, ra.y, ra.z, ra.w, rb.x, rb.y};
                #pragma unroll
                for (int p = 0; p < 6; p++) {
                    float2 v2 = __bfloat1622float2(
                        *reinterpret_cast<__nv_bfloat162*>(&wds[p]));
                    f[2 * p]     = v2.x * w;
                    f[2 * p + 1] = v2.y * w;
                }
            }
            #pragma unroll
            for (int r = 4; r >= 1; r >>= 1) {
                #pragma unroll
                for (int j = 0; j < 12; j++)
                    f[j] += __shfl_xor_sync(0xffffffffu, f[j], r);
            }
            if (g_c3 == 0) {
                unsigned int o[8];
                #pragma unroll
                for (int p = 0; p < 6; p++) o[p] = packbf2(f[2 * p], f[2 * p + 1]);
                o[6] = 0u; o[7] = 0u;   // zero-pad k=12..15
                uint4* dst = reinterpret_cast<uint4*>(&s_xb[g_ss * 24]);
                dst[0] = make_uint4(o[0], o[1], o[2], o[3]);
                dst[1] = make_uint4(o[4], o[5], o[6], o[7]);
            }
        }
        __syncthreads();

        // ---- layer 0: [16x16] x [16x128] ----
        unsigned int a0, a1, a2, a3;
        LDSM4(a0, a1, a2, a3, xaddr);
        float C0[4][4];
        #pragma unroll
        for (int nt = 0; nt < 4; nt++) {
            C0[nt][0] = 0.0f; C0[nt][1] = 0.0f; C0[nt][2] = 0.0f; C0[nt][3] = 0.0f;
            MMA_BF16(C0[nt], a0, a1, a2, a3, B0f[nt][0], B0f[nt][1]);
        }
        // add vw, relu, store h0 (bf16) to s_h
        #pragma unroll
        for (int nt = 0; nt < 4; nt++) {
            int cc = nbase + nt * 8 + 2 * tq;
            float v0 = s_vw[cc], v1 = s_vw[cc + 1];
            unsigned int wlo = packbf2(fmaxf(C0[nt][0] + v0, 0.0f),
                                       fmaxf(C0[nt][1] + v1, 0.0f));
            unsigned int whi = packbf2(fmaxf(C0[nt][2] + v0, 0.0f),
                                       fmaxf(C0[nt][3] + v1, 0.0f));
            *reinterpret_cast<unsigned int*>(&s_h[gq * 136 + cc]) = wlo;
            *reinterpret_cast<unsigned int*>(&s_h[(gq + 8) * 136 + cc]) = whi;
        }
        __syncthreads();

        // ---- layer 1: [16x128] x [128x128] ----
        float C1[4][4];
        #pragma unroll
        for (int nt = 0; nt < 4; nt++) {
            C1[nt][0] = b1lo[nt]; C1[nt][1] = b1hi[nt];
            C1[nt][2] = b1lo[nt]; C1[nt][3] = b1hi[nt];
        }
        #pragma unroll
        for (int ks = 0; ks < 8; ks++) {
            unsigned int h0, h1, h2, h3;
            LDSM4(h0, h1, h2, h3, haddr0 + ks * 32);
            #pragma unroll
            for (int nt = 0; nt < 4; nt++)
                MMA_BF16(C1[nt], h0, h1, h2, h3, B1[nt][ks][0], B1[nt][ks][1]);
        }
        __syncthreads();   // everyone done reading h0
        #pragma unroll
        for (int nt = 0; nt < 4; nt++) {
            int cc = nbase + nt * 8 + 2 * tq;
            unsigned int wlo = packbf2(fmaxf(C1[nt][0], 0.0f), fmaxf(C1[nt][1], 0.0f));
            unsigned int whi = packbf2(fmaxf(C1[nt][2], 0.0f), fmaxf(C1[nt][3], 0.0f));
            *reinterpret_cast<unsigned int*>(&s_h[gq * 136 + cc]) = wlo;
            *reinterpret_cast<unsigned int*>(&s_h[(gq + 8) * 136 + cc]) = whi;
        }
        __syncthreads();

        // ---- layer 2 (warp 0 only): [16x128] x [128x8(3 real)] + epilogue
        if (wid == 0) {
            float C2[4] = {bias2, bias2b, bias2, bias2b};
            #pragma unroll
            for (int ks = 0; ks < 8; ks++) {
                unsigned int h0, h1, h2, h3;
                LDSM4(h0, h1, h2, h3, haddr0 + ks * 32);
                unsigned int wb0 = g_w2p[gq * 64 + ks * 8 + tq];
                unsigned int wb1 = g_w2p[gq * 64 + ks * 8 + 4 + tq];
                MMA_BF16(C2, h0, h1, h2, h3, wb0, wb1);
            }
            float wlo = s_wgt[s0 + gq];
            float whi = s_wgt[s0 + 8 + gq];
            int col0 = 2 * tq;
            if (col0 < 3) {
                racc0 += wlo * sigm(C2[0]);
                racc2 += whi * sigm(C2[2]);
            }
            if (col0 + 1 < 3) {
                racc1 += wlo * sigm(C2[1]);
                racc3 += whi * sigm(C2[3]);
            }
        }
        // next-tile loop-top __syncthreads_or orders warp0's s_h reads
        // before the next layer-0 overwrite.
    }

    // fold per-lane accumulators into s_acc
    if (wid == 0) {
        int col0 = 2 * tq;
        if (col0 < 3)     atomicAdd(&s_acc[col0],     racc0 + racc2);
        if (col0 + 1 < 3) atomicAdd(&s_acc[col0 + 1], racc1 + racc3);
    }
    __syncthreads();
    if (tid < 3) out[ray * 3 + tid] = s_acc[tid] + s_ainv;
}

extern "C" void kernel_launch(void* const* d_in, const int* in_sizes, int n_in,
                              void* d_out, int out_size)
{
    const float* rays_o = (const float*)d_in[0];
    const float* rays_d = (const float*)d_in[1];
    const float* dens   = (const float*)d_in[2];
    const float* feat   = (const float*)d_in[3];
    const float* w0     = (const float*)d_in[4];
    const float* b0     = (const float*)d_in[5];
    const float* w1     = (const float*)d_in[6];
    const float* b1     = (const float*)d_in[7];
    const float* w2     = (const float*)d_in[8];
    const float* b2     = (const float*)d_in[9];
    float* out = (float*)d_out;

    prep_kernel<<<32, 256>>>(w0, w1, w2);
    relayout_kernel<<<RES3 / 256, 256>>>(feat);
    dvgo_kernel<<<NRAYS, 128>>>(rays_o, rays_d, dens, feat,
                                w0, b0, w1, b1, w2, b2, out);
}

// round 9
// speedup vs baseline: 4.8623x; 1.3128x over previous
#include <cuda_runtime.h>
#include <cuda_bf16.h>
#include <math.h>

#define NRAYS 4096
#define NS    256
#define RES   160
#define RES2  (RES*RES)
#define RES3  (RES*RES*RES)
#define TNEAR 0.05f
#define TFAR  2.0f
#define ACT_SHIFT (-13.8155095579f)
#define WEPS  1e-9f

// packed bf16x2 weight fragments: [n][kpair], low half = even k
__device__ unsigned int g_w0p[128 * 8];    // layer0: k 0..15 (12 real, 4 zero)
__device__ unsigned int g_w1p[128 * 64];   // layer1: k 0..127
__device__ unsigned int g_w2p[8 * 64];     // layer2: n 0..7 (3 real, 5 zero)

// channel-interleaved feature grid: 32B record per voxel = 12 bf16 + 4 pad
__device__ __align__(16) unsigned int g_pack[RES3 * 8];   // 131 MB static

__device__ __forceinline__ unsigned int packbf2(float lo, float hi) {
    __nv_bfloat162 h = __floats2bfloat162_rn(lo, hi);
    return *reinterpret_cast<unsigned int*>(&h);
}

__global__ void prep_kernel(const float* __restrict__ w0,
                            const float* __restrict__ w1,
                            const float* __restrict__ w2)
{
    int i = blockIdx.x * 256 + threadIdx.x;
    if (i < 128 * 64) {
        int n = i >> 6, p = i & 63;
        g_w1p[i] = packbf2(w1[(2 * p) * 128 + n], w1[(2 * p + 1) * 128 + n]);
    }
    if (i < 128 * 8) {
        int n = i >> 3, p = i & 7;
        int k0 = 2 * p, k1 = 2 * p + 1;
        float lo = (k0 < 12) ? w0[k0 * 128 + n] : 0.0f;
        float hi = (k1 < 12) ? w0[k1 * 128 + n] : 0.0f;
        g_w0p[i] = packbf2(lo, hi);
    }
    if (i < 8 * 64) {
        int n = i >> 6, p = i & 63;
        float lo = (n < 3) ? w2[(2 * p) * 3 + n] : 0.0f;
        float hi = (n < 3) ? w2[(2 * p + 1) * 3 + n] : 0.0f;
        g_w2p[i] = packbf2(lo, hi);
    }
}

__global__ void relayout_kernel(const float* __restrict__ feat)
{
    int v = blockIdx.x * 256 + threadIdx.x;
    if (v >= RES3) return;
    unsigned int r[8];
    #pragma unroll
    for (int p = 0; p < 6; p++)
        r[p] = packbf2(feat[(2 * p) * RES3 + v], feat[(2 * p + 1) * RES3 + v]);
    r[6] = 0u; r[7] = 0u;
    uint4* dst = reinterpret_cast<uint4*>(g_pack) + (size_t)v * 2;
    dst[0] = make_uint4(r[0], r[1], r[2], r[3]);
    dst[1] = make_uint4(r[4], r[5], r[6], r[7]);
}

#define LDSM4(A0,A1,A2,A3,addr) \
    asm volatile("ldmatrix.sync.aligned.m8n8.x4.shared.b16 {%0,%1,%2,%3}, [%4];" \
        : "=r"(A0), "=r"(A1), "=r"(A2), "=r"(A3) : "r"(addr))

#define MMA_BF16(C,A0,A1,A2,A3,B0r,B1r) \
    asm volatile("mma.sync.aligned.m16n8k16.row.col.f32.bf16.bf16.f32 " \
        "{%0,%1,%2,%3}, {%4,%5,%6,%7}, {%8,%9}, {%0,%1,%2,%3};" \
        : "+f"((C)[0]), "+f"((C)[1]), "+f"((C)[2]), "+f"((C)[3]) \
        : "r"(A0), "r"(A1), "r"(A2), "r"(A3), "r"(B0r), "r"(B1r))

__device__ __forceinline__ void tri_setup(float px, float py, float pz,
                                          int& base, float& fx, float& fy, float& fz)
{
    float ix = fminf(fmaxf((px + 1.0f) * 79.5f, 0.0f), 159.0f);
    float iy = fminf(fmaxf((py + 1.0f) * 79.5f, 0.0f), 159.0f);
    float iz = fminf(fmaxf((pz + 1.0f) * 79.5f, 0.0f), 159.0f);
    int x0 = min((int)ix, 158);
    int y0 = min((int)iy, 158);
    int z0 = min((int)iz, 158);
    fx = ix - (float)x0;
    fy = iy - (float)y0;
    fz = iz - (float)z0;
    base = x0 * RES2 + y0 * RES + z0;
}

__device__ __forceinline__ float tri_fetch(const float* __restrict__ g, int base,
                                           float fx, float fy, float fz)
{
    float c000 = g[base];
    float c001 = g[base + 1];
    float c010 = g[base + RES];
    float c011 = g[base + RES + 1];
    const float* g1 = g + base + RES2;
    float c100 = g1[0];
    float c101 = g1[1];
    float c110 = g1[RES];
    float c111 = g1[RES + 1];
    float gz = 1.0f - fz;
    float c00 = c000 * gz + c001 * fz;
    float c01 = c010 * gz + c011 * fz;
    float c10 = c100 * gz + c101 * fz;
    float c11 = c110 * gz + c111 * fz;
    float gy = 1.0f - fy;
    float c0 = c00 * gy + c01 * fy;
    float c1 = c10 * gy + c11 * fy;
    return c0 * (1.0f - fx) + c1 * fx;
}

__device__ __forceinline__ float sigm(float x) { return 1.0f / (1.0f + expf(-x)); }

// issue the two corner loads (pass0: sample css, pass1: css+16) for a tile
__device__ __forceinline__ void fetch_tile(
    int s0, int css, int dx, int dy, int dz,
    float ox, float oy, float oz, float vx, float vy, float vz, float tstep,
    uint4& ra0, uint4& rb0, float& w0v,
    uint4& ra1, uint4& rb1, float& w1v)
{
    #pragma unroll
    for (int p = 0; p < 2; p++) {
        int ss = s0 + css + p * 16;
        float t = TNEAR + (float)ss * tstep;
        float px = ox + vx * t, py = oy + vy * t, pz = oz + vz * t;
        int base; float fx, fy, fz;
        tri_setup(px, py, pz, base, fx, fy, fz);
        float w = (dx ? fx : 1.0f - fx) * (dy ? fy : 1.0f - fy) * (dz ? fz : 1.0f - fz);
        const uint4* rec = reinterpret_cast<const uint4*>(g_pack) +
            (size_t)(base + dx * RES2 + dy * RES + dz) * 2;
        if (p == 0) { ra0 = rec[0]; rb0 = rec[1]; w0v = w; }
        else        { ra1 = rec[0]; rb1 = rec[1]; w1v = w; }
    }
}

// weighted shfl-reduce over 8 corner lanes; lane c3==0 stores sample row
__device__ __forceinline__ void reduce_store(
    uint4 ra, uint4 rb, float w, int row, int c3, __nv_bfloat16* s_xb)
{
    float f[12];
    unsigned int wds[6] = {ra.x, ra.y, ra.z, ra.w, rb.x, rb.y};
    #pragma unroll
    for (int p = 0; p < 6; p++) {
        float2 v2 = __bfloat1622float2(*reinterpret_cast<__nv_bfloat162*>(&wds[p]));
        f[2 * p]     = v2.x * w;
        f[2 * p + 1] = v2.y * w;
    }
    #pragma unroll
    for (int r = 4; r >= 1; r >>= 1) {
        #pragma unroll
        for (int j = 0; j < 12; j++)
            f[j] += __shfl_xor_sync(0xffffffffu, f[j], r);
    }
    if (c3 == 0) {
        unsigned int o[8];
        #pragma unroll
        for (int p = 0; p < 6; p++) o[p] = packbf2(f[2 * p], f[2 * p + 1]);
        o[6] = 0u; o[7] = 0u;
        uint4* dst = reinterpret_cast<uint4*>(&s_xb[row * 24]);
        dst[0] = make_uint4(o[0], o[1], o[2], o[3]);
        dst[1] = make_uint4(o[4], o[5], o[6], o[7]);
    }
}

// --- main fused kernel: one block (128 threads) per ray --------------------
// 8 tiles x 32 samples; prefetched gather; double-buffered h; parallel scan.
__global__ __launch_bounds__(128)
void dvgo_kernel(const float* __restrict__ rays_o, const float* __restrict__ rays_d,
                 const float* __restrict__ dens,  const float* __restrict__ feat,
                 const float* __restrict__ w0,    const float* __restrict__ b0,
                 const float* __restrict__ w1,    const float* __restrict__ b1,
                 const float* __restrict__ w2,    const float* __restrict__ b2,
                 float* __restrict__ out)
{
    __shared__ __align__(16) __nv_bfloat16 s_h0[32 * 136];
    __shared__ __align__(16) __nv_bfloat16 s_h1[32 * 136];
    __shared__ __align__(16) __nv_bfloat16 s_xb[32 * 24];
    __shared__ float s_vw[128];
    __shared__ float s_vemb[27];
    __shared__ float s_wgt[NS];
    __shared__ float s_wtot[4];
    __shared__ int   s_any[8];
    __shared__ int   s_list[8];
    __shared__ int   s_nact;
    __shared__ float s_acc[3];
    __shared__ float s_ainv;

    const int ray = blockIdx.x;
    const int tid = threadIdx.x;
    const int wid = tid >> 5;
    const int lane = tid & 31;
    const int gq = lane >> 2;
    const int tq = lane & 3;

    const float ox = rays_o[ray * 3 + 0];
    const float oy = rays_o[ray * 3 + 1];
    const float oz = rays_o[ray * 3 + 2];
    float rdx = rays_d[ray * 3 + 0];
    float rdy = rays_d[ray * 3 + 1];
    float rdz = rays_d[ray * 3 + 2];
    const float invn = rsqrtf(rdx * rdx + rdy * rdy + rdz * rdz);
    const float vx = rdx * invn, vy = rdy * invn, vz = rdz * invn;

    // view embedding
    if (tid < 27) {
        float val;
        if (tid < 3) {
            val = (tid == 0) ? vx : ((tid == 1) ? vy : vz);
        } else if (tid < 15) {
            int k = tid - 3;
            int d = k >> 2, f = k & 3;
            float v = (d == 0) ? vx : ((d == 1) ? vy : vz);
            val = sinf(v * (float)(1 << f));
        } else {
            int k = tid - 15;
            int d = k >> 2, f = k & 3;
            float v = (d == 0) ? vx : ((d == 1) ? vy : vz);
            val = cosf(v * (float)(1 << f));
        }
        s_vemb[tid] = val;
    }
    if (tid < 3) s_acc[tid] = 0.0f;
    if (tid < 8) s_any[tid] = 0;
    __syncthreads();

    // fold view embedding through w0 (fp32)
    {
        float vw = b0[tid];
        #pragma unroll
        for (int k = 0; k < 27; k++) vw += s_vemb[k] * w0[(12 + k) * 128 + tid];
        s_vw[tid] = vw;
    }

    // ---- alpha for 2 consecutive samples per thread ----------------------
    const float tstep = (TFAR - TNEAR) / 255.0f;
    float a0, a1;
    #pragma unroll
    for (int p = 0; p < 2; p++) {
        int s = 2 * tid + p;
        float t = TNEAR + (float)s * tstep;
        float px = ox + vx * t, py = oy + vy * t, pz = oz + vz * t;
        bool inbox = (px >= -1.0f) & (px <= 1.0f) &
                     (py >= -1.0f) & (py <= 1.0f) &
                     (pz >= -1.0f) & (pz <= 1.0f);
        float alpha = 0.0f;
        if (inbox) {
            int base; float fx, fy, fz;
            tri_setup(px, py, pz, base, fx, fy, fz);
            float d = tri_fetch(dens, base, fx, fy, fz);
            float e = expf(d + ACT_SHIFT);
            alpha = -expm1f(-0.5f * log1pf(e));
        }
        if (p == 0) a0 = alpha; else a1 = alpha;
    }

    // ---- parallel transmittance scan -------------------------------------
    const float m0 = 1.0f - a0, m1 = 1.0f - a1;
    float sc = m0 * m1;               // pair product
    const float prod = sc;
    #pragma unroll
    for (int off = 1; off < 32; off <<= 1) {
        float v = __shfl_up_sync(0xffffffffu, sc, off);
        if (lane >= off) sc *= v;
    }
    float excl = __shfl_up_sync(0xffffffffu, sc, 1);
    if (lane == 0) excl = 1.0f;
    if (lane == 31) s_wtot[wid] = sc;
    (void)prod;
    __syncthreads();
    {
        float pre = 1.0f;
        #pragma unroll
        for (int w = 0; w < 4; w++) if (w < wid) pre *= s_wtot[w];
        float Te = pre * excl;
        float w0s = a0 * Te;
        float w1s = a1 * Te * m0;
        s_wgt[2 * tid]     = w0s;
        s_wgt[2 * tid + 1] = w1s;
        if ((w0s > WEPS) | (w1s > WEPS)) s_any[tid >> 4] = 1;  // tile = (2*tid)>>5
        if (tid == 0) s_ainv = s_wtot[0] * s_wtot[1] * s_wtot[2] * s_wtot[3];
    }
    __syncthreads();
    if (tid == 0) {
        int n = 0;
        #pragma unroll
        for (int tl = 0; tl < 8; tl++) if (s_any[tl]) s_list[n++] = tl;
        s_nact = n;
    }

    // ---- resident B fragments (w0, w1) -----------------------------------
    const int nbase = wid * 32;
    unsigned int B1[4][8][2];
    unsigned int B0f[4][2];
    #pragma unroll
    for (int nt = 0; nt < 4; nt++) {
        int n = nbase + nt * 8 + gq;
        #pragma unroll
        for (int ks = 0; ks < 8; ks++) {
            B1[nt][ks][0] = g_w1p[n * 64 + ks * 8 + tq];
            B1[nt][ks][1] = g_w1p[n * 64 + ks * 8 + 4 + tq];
        }
        B0f[nt][0] = g_w0p[n * 8 + tq];
        B0f[nt][1] = g_w0p[n * 8 + 4 + tq];
    }
    float b1lo[4], b1hi[4];
    #pragma unroll
    for (int nt = 0; nt < 4; nt++) {
        int c0 = nbase + nt * 8 + 2 * tq;
        b1lo[nt] = b1[c0];
        b1hi[nt] = b1[c0 + 1];
    }
    const float bias2  = (2 * tq < 3) ? b2[2 * tq] : 0.0f;
    const float bias2b = (2 * tq + 1 < 3) ? b2[2 * tq + 1] : 0.0f;

    // ldmatrix per-lane addresses
    const unsigned int xb_base = (unsigned int)__cvta_generic_to_shared(s_xb);
    const unsigned int h0_base = (unsigned int)__cvta_generic_to_shared(s_h0);
    const unsigned int h1_base = (unsigned int)__cvta_generic_to_shared(s_h1);
    const int lrow = (((lane >> 3) & 1) << 3) + (lane & 7);
    const int lch  = (lane >> 4) & 1;

    // gather identity: 8 threads per sample
    const int g_css = tid >> 3;          // 0..15
    const int g_c3 = tid & 7;
    const int g_dz = g_c3 & 1;
    const int g_dy = (g_c3 >> 1) & 1;
    const int g_dx = (g_c3 >> 2) & 1;

    float racc0 = 0.0f, racc1 = 0.0f, racc2 = 0.0f, racc3 = 0.0f;

    __syncthreads();
    const int nact = s_nact;

    // prefetch first active tile
    uint4 cra0, crb0, cra1, crb1;
    float cw0, cw1;
    if (nact > 0)
        fetch_tile(s_list[0] * 32, g_css, g_dx, g_dy, g_dz,
                   ox, oy, oz, vx, vy, vz, tstep,
                   cra0, crb0, cw0, cra1, crb1, cw1);

    for (int i = 0; i < nact; i++) {
        const int s0 = s_list[i] * 32;

        // issue next tile's loads first (they fly during reduce + MMA)
        uint4 nra0, nrb0, nra1, nrb1;
        float nw0, nw1;
        if (i + 1 < nact)
            fetch_tile(s_list[i + 1] * 32, g_css, g_dx, g_dy, g_dz,
                       ox, oy, oz, vx, vy, vz, tstep,
                       nra0, nrb0, nw0, nra1, nrb1, nw1);

        // reduce current tile into s_xb (rows 0..31)
        reduce_store(cra0, crb0, cw0, g_css,      g_c3, s_xb);
        reduce_store(cra1, crb1, cw1, g_css + 16, g_c3, s_xb);
        __syncthreads();

        // ---- layer 0: two m16 halves ----
        #pragma unroll
        for (int mh = 0; mh < 2; mh++) {
            unsigned int a0r, a1r, a2r, a3r;
            LDSM4(a0r, a1r, a2r, a3r, xb_base + (mh * 16 + lrow) * 48 + lch * 16);
            #pragma unroll
            for (int nt = 0; nt < 4; nt++) {
                float C0[4] = {0.0f, 0.0f, 0.0f, 0.0f};
                MMA_BF16(C0, a0r, a1r, a2r, a3r, B0f[nt][0], B0f[nt][1]);
                int cc = nbase + nt * 8 + 2 * tq;
                float v0 = s_vw[cc], v1 = s_vw[cc + 1];
                unsigned int wlo = packbf2(fmaxf(C0[0] + v0, 0.0f),
                                           fmaxf(C0[1] + v1, 0.0f));
                unsigned int whi = packbf2(fmaxf(C0[2] + v0, 0.0f),
                                           fmaxf(C0[3] + v1, 0.0f));
                *reinterpret_cast<unsigned int*>(&s_h0[(mh * 16 + gq) * 136 + cc]) = wlo;
                *reinterpret_cast<unsigned int*>(&s_h0[(mh * 16 + 8 + gq) * 136 + cc]) = whi;
            }
        }
        __syncthreads();

        // ---- layer 1: two m16 halves, B1 register-resident ----
        #pragma unroll
        for (int mh = 0; mh < 2; mh++) {
            float C1[4][4];
            #pragma unroll
            for (int nt = 0; nt < 4; nt++) {
                C1[nt][0] = b1lo[nt]; C1[nt][1] = b1hi[nt];
                C1[nt][2] = b1lo[nt]; C1[nt][3] = b1hi[nt];
            }
            #pragma unroll
            for (int ks = 0; ks < 8; ks++) {
                unsigned int h0r, h1r, h2r, h3r;
                LDSM4(h0r, h1r, h2r, h3r,
                      h0_base + (mh * 16 + lrow) * 272 + ks * 32);
                #pragma unroll
                for (int nt = 0; nt < 4; nt++)
                    MMA_BF16(C1[nt], h0r, h1r, h2r, h3r, B1[nt][ks][0], B1[nt][ks][1]);
            }
            #pragma unroll
            for (int nt = 0; nt < 4; nt++) {
                int cc = nbase + nt * 8 + 2 * tq;
                unsigned int wlo = packbf2(fmaxf(C1[nt][0], 0.0f), fmaxf(C1[nt][1], 0.0f));
                unsigned int whi = packbf2(fmaxf(C1[nt][2], 0.0f), fmaxf(C1[nt][3], 0.0f));
                *reinterpret_cast<unsigned int*>(&s_h1[(mh * 16 + gq) * 136 + cc]) = wlo;
                *reinterpret_cast<unsigned int*>(&s_h1[(mh * 16 + 8 + gq) * 136 + cc]) = whi;
            }
        }
        __syncthreads();

        // ---- layer 2: warps 0,1 take one m16 half each ----
        if (wid < 2) {
            const int mh = wid;
            float C2[4] = {bias2, bias2b, bias2, bias2b};
            #pragma unroll
            for (int ks = 0; ks < 8; ks++) {
                unsigned int h0r, h1r, h2r, h3r;
                LDSM4(h0r, h1r, h2r, h3r,
                      h1_base + (mh * 16 + lrow) * 272 + ks * 32);
                unsigned int wb0 = g_w2p[gq * 64 + ks * 8 + tq];
                unsigned int wb1 = g_w2p[gq * 64 + ks * 8 + 4 + tq];
                MMA_BF16(C2, h0r, h1r, h2r, h3r, wb0, wb1);
            }
            float wlo = s_wgt[s0 + mh * 16 + gq];
            float whi = s_wgt[s0 + mh * 16 + 8 + gq];
            int col0 = 2 * tq;
            if (col0 < 3) {
                racc0 += wlo * sigm(C2[0]);
                racc2 += whi * sigm(C2[2]);
            }
            if (col0 + 1 < 3) {
                racc1 += wlo * sigm(C2[1]);
                racc3 += whi * sigm(C2[3]);
            }
        }

        // rotate prefetch
        cra0 = nra0; crb0 = nrb0; cw0 = nw0;
        cra1 = nra1; crb1 = nrb1; cw1 = nw1;
    }

    if (wid < 2) {
        int col0 = 2 * tq;
        if (col0 < 3)     atomicAdd(&s_acc[col0],     racc0 + racc2);
        if (col0 + 1 < 3) atomicAdd(&s_acc[col0 + 1], racc1 + racc3);
    }
    __syncthreads();
    if (tid < 3) out[ray * 3 + tid] = s_acc[tid] + s_ainv;
}

extern "C" void kernel_launch(void* const* d_in, const int* in_sizes, int n_in,
                              void* d_out, int out_size)
{
    const float* rays_o = (const float*)d_in[0];
    const float* rays_d = (const float*)d_in[1];
    const float* dens   = (const float*)d_in[2];
    const float* feat   = (const float*)d_in[3];
    const float* w0     = (const float*)d_in[4];
    const float* b0     = (const float*)d_in[5];
    const float* w1     = (const float*)d_in[6];
    const float* b1     = (const float*)d_in[7];
    const float* w2     = (const float*)d_in[8];
    const float* b2     = (const float*)d_in[9];
    float* out = (float*)d_out;

    prep_kernel<<<32, 256>>>(w0, w1, w2);
    relayout_kernel<<<RES3 / 256, 256>>>(feat);
    dvgo_kernel<<<NRAYS, 128>>>(rays_o, rays_d, dens, feat,
                                w0, b0, w1, b1, w2, b2, out);
}

// round 11
// speedup vs baseline: 5.9702x; 1.2278x over previous
#include <cuda_runtime.h>
#include <cuda_bf16.h>
#include <cuda_fp16.h>
#include <cuda_fp8.h>
#include <math.h>

#define NRAYS 4096
#define NS    256
#define RES   160
#define RES2  (RES*RES)
#define RES3  (RES*RES*RES)
#define TNEAR 0.05f
#define TFAR  2.0f
#define ACT_SHIFT (-13.8155095579f)
#define WEPS  1e-9f

// packed bf16x2 weight fragments: [n][kpair], low half = even k
__device__ unsigned int g_w0p[128 * 8];    // layer0 (feature part / 16)
__device__ unsigned int g_w1p[128 * 64];   // layer1
__device__ unsigned int g_w2p[8 * 64];     // layer2

// fp8 channel-interleaved feature grid: 16B record = 12 e4m3 (x16 scaled) + 4 pad
__device__ __align__(16) unsigned int g_pack[RES3 * 4];   // 65.5 MB

__device__ __forceinline__ unsigned int packbf2(float lo, float hi) {
    __nv_bfloat162 h = __floats2bfloat162_rn(lo, hi);
    return *reinterpret_cast<unsigned int*>(&h);
}

__global__ void prep_kernel(const float* __restrict__ w0,
                            const float* __restrict__ w1,
                            const float* __restrict__ w2)
{
    int i = blockIdx.x * 256 + threadIdx.x;
    if (i < 128 * 64) {
        int n = i >> 6, p = i & 63;
        g_w1p[i] = packbf2(w1[(2 * p) * 128 + n], w1[(2 * p + 1) * 128 + n]);
    }
    if (i < 128 * 8) {             // w0 feature rows carry the 1/16 descale
        int n = i >> 3, p = i & 7;
        int k0 = 2 * p, k1 = 2 * p + 1;
        float lo = (k0 < 12) ? w0[k0 * 128 + n] * 0.0625f : 0.0f;
        float hi = (k1 < 12) ? w0[k1 * 128 + n] * 0.0625f : 0.0f;
        g_w0p[i] = packbf2(lo, hi);
    }
    if (i < 8 * 64) {
        int n = i >> 6, p = i & 63;
        float lo = (n < 3) ? w2[(2 * p) * 3 + n] : 0.0f;
        float hi = (n < 3) ? w2[(2 * p + 1) * 3 + n] : 0.0f;
        g_w2p[i] = packbf2(lo, hi);
    }
}

// [12][RES3] fp32 -> [RES3] 16B fp8 records (value*16, e4m3)
__global__ void relayout_kernel(const float* __restrict__ feat)
{
    int v = blockIdx.x * 256 + threadIdx.x;
    if (v >= RES3) return;
    unsigned int r[3];
    #pragma unroll
    for (int p = 0; p < 3; p++) {
        unsigned int w = 0;
        #pragma unroll
        for (int j = 0; j < 4; j++) {
            int c = 4 * p + j;
            unsigned int b = (unsigned int)__nv_cvt_float_to_fp8(
                feat[c * RES3 + v] * 16.0f, __NV_SATFINITE, __NV_E4M3);
            w |= b << (8 * j);
        }
        r[p] = w;
    }
    reinterpret_cast<uint4*>(g_pack)[v] = make_uint4(r[0], r[1], r[2], 0u);
}

#define LDSM4(A0,A1,A2,A3,addr) \
    asm volatile("ldmatrix.sync.aligned.m8n8.x4.shared.b16 {%0,%1,%2,%3}, [%4];" \
        : "=r"(A0), "=r"(A1), "=r"(A2), "=r"(A3) : "r"(addr))

#define MMA_BF16(C,A0,A1,A2,A3,B0r,B1r) \
    asm volatile("mma.sync.aligned.m16n8k16.row.col.f32.bf16.bf16.f32 " \
        "{%0,%1,%2,%3}, {%4,%5,%6,%7}, {%8,%9}, {%0,%1,%2,%3};" \
        : "+f"((C)[0]), "+f"((C)[1]), "+f"((C)[2]), "+f"((C)[3]) \
        : "r"(A0), "r"(A1), "r"(A2), "r"(A3), "r"(B0r), "r"(B1r))

#define CP_ASYNC16(dst, src) \
    asm volatile("cp.async.cg.shared.global [%0], [%1], 16;" \
        :: "r"(dst), "l"(src))
#define CP_COMMIT() asm volatile("cp.async.commit_group;")

__device__ __forceinline__ void tri_setup(float px, float py, float pz,
                                          int& base, float& fx, float& fy, float& fz)
{
    float ix = fminf(fmaxf((px + 1.0f) * 79.5f, 0.0f), 159.0f);
    float iy = fminf(fmaxf((py + 1.0f) * 79.5f, 0.0f), 159.0f);
    float iz = fminf(fmaxf((pz + 1.0f) * 79.5f, 0.0f), 159.0f);
    int x0 = min((int)ix, 158);
    int y0 = min((int)iy, 158);
    int z0 = min((int)iz, 158);
    fx = ix - (float)x0;
    fy = iy - (float)y0;
    fz = iz - (float)z0;
    base = x0 * RES2 + y0 * RES + z0;
}

__device__ __forceinline__ float tri_fetch(const float* __restrict__ g, int base,
                                           float fx, float fy, float fz)
{
    float c000 = g[base];
    float c001 = g[base + 1];
    float c010 = g[base + RES];
    float c011 = g[base + RES + 1];
    const float* g1 = g + base + RES2;
    float c100 = g1[0];
    float c101 = g1[1];
    float c110 = g1[RES];
    float c111 = g1[RES + 1];
    float gz = 1.0f - fz;
    float c00 = c000 * gz + c001 * fz;
    float c01 = c010 * gz + c011 * fz;
    float c10 = c100 * gz + c101 * fz;
    float c11 = c110 * gz + c111 * fz;
    float gy = 1.0f - fy;
    float c0 = c00 * gy + c01 * fy;
    float c1 = c10 * gy + c11 * fy;
    return c0 * (1.0f - fx) + c1 * fx;
}

__device__ __forceinline__ float sigm(float x) { return 1.0f / (1.0f + expf(-x)); }

__device__ __forceinline__ void fp8x4_to_f4(unsigned int w, float* f)
{
    __half2_raw h0 = __nv_cvt_fp8x2_to_halfraw2(
        (__nv_fp8x2_storage_t)(w & 0xFFFFu), __NV_E4M3);
    __half2_raw h1 = __nv_cvt_fp8x2_to_halfraw2(
        (__nv_fp8x2_storage_t)(w >> 16), __NV_E4M3);
    float2 a = __half22float2(*reinterpret_cast<__half2*>(&h0));
    float2 b = __half22float2(*reinterpret_cast<__half2*>(&h1));
    f[0] = a.x; f[1] = a.y; f[2] = b.x; f[3] = b.y;
}

// issue cp.async for the two corner records of this thread for one tile;
// trilerp weights returned in registers.
__device__ __forceinline__ void fetch_tile_async(
    int s0, int css, int c3, int dx, int dy, int dz,
    float ox, float oy, float oz, float vx, float vy, float vz, float tstep,
    unsigned int cbuf, float& w0v, float& w1v)
{
    #pragma unroll
    for (int p = 0; p < 2; p++) {
        int ss = css + p * 16;
        float t = TNEAR + (float)(s0 + ss) * tstep;
        float px = ox + vx * t, py = oy + vy * t, pz = oz + vz * t;
        int base; float fx, fy, fz;
        tri_setup(px, py, pz, base, fx, fy, fz);
        float w = (dx ? fx : 1.0f - fx) * (dy ? fy : 1.0f - fy) * (dz ? fz : 1.0f - fz);
        const unsigned int* src = g_pack +
            (size_t)(base + dx * RES2 + dy * RES + dz) * 4;
        unsigned int dst = cbuf + (unsigned int)(ss * 8 + c3) * 16;
        CP_ASYNC16(dst, src);
        if (p == 0) w0v = w; else w1v = w;
    }
}

// convert own fp8 record, weight, shfl-reduce over 8 corner lanes, store row
__device__ __forceinline__ void reduce_store_fp8(
    const uint4* rec_p, float w, int row, int c3, __nv_bfloat16* s_xb)
{
    uint4 rec = *rec_p;
    float f[12];
    fp8x4_to_f4(rec.x, f);
    fp8x4_to_f4(rec.y, f + 4);
    fp8x4_to_f4(rec.z, f + 8);
    #pragma unroll
    for (int j = 0; j < 12; j++) f[j] *= w;
    #pragma unroll
    for (int r = 4; r >= 1; r >>= 1) {
        #pragma unroll
        for (int j = 0; j < 12; j++)
            f[j] += __shfl_xor_sync(0xffffffffu, f[j], r);
    }
    if (c3 == 0) {
        unsigned int o[8];
        #pragma unroll
        for (int p = 0; p < 6; p++) o[p] = packbf2(f[2 * p], f[2 * p + 1]);
        o[6] = 0u; o[7] = 0u;
        uint4* dst = reinterpret_cast<uint4*>(&s_xb[row * 24]);
        dst[0] = make_uint4(o[0], o[1], o[2], o[3]);
        dst[1] = make_uint4(o[4], o[5], o[6], o[7]);
    }
}

// --- main fused kernel: one block (128 threads) per ray --------------------
__global__ __launch_bounds__(128, 4)
void dvgo_kernel(const float* __restrict__ rays_o, const float* __restrict__ rays_d,
                 const float* __restrict__ dens,  const float* __restrict__ feat,
                 const float* __restrict__ w0,    const float* __restrict__ b0,
                 const float* __restrict__ w1,    const float* __restrict__ b1,
                 const float* __restrict__ w2,    const float* __restrict__ b2,
                 float* __restrict__ out)
{
    __shared__ __align__(16) __nv_bfloat16 s_h0[32 * 136];
    __shared__ __align__(16) __nv_bfloat16 s_h1[32 * 136];
    __shared__ __align__(16) __nv_bfloat16 s_xb[32 * 24];
    __shared__ __align__(16) uint4 s_corner[2][256];   // 2 x 4KB fp8 records
    __shared__ float s_vw[128];
    __shared__ float s_vemb[27];
    __shared__ float s_wgt[NS];
    __shared__ float s_wtot[4];
    __shared__ int   s_any[8];
    __shared__ int   s_list[8];
    __shared__ int   s_nact;
    __shared__ float s_acc[3];
    __shared__ float s_ainv;

    const int ray = blockIdx.x;
    const int tid = threadIdx.x;
    const int wid = tid >> 5;
    const int lane = tid & 31;
    const int gq = lane >> 2;
    const int tq = lane & 3;

    const float ox = rays_o[ray * 3 + 0];
    const float oy = rays_o[ray * 3 + 1];
    const float oz = rays_o[ray * 3 + 2];
    float rdx = rays_d[ray * 3 + 0];
    float rdy = rays_d[ray * 3 + 1];
    float rdz = rays_d[ray * 3 + 2];
    const float invn = rsqrtf(rdx * rdx + rdy * rdy + rdz * rdz);
    const float vx = rdx * invn, vy = rdy * invn, vz = rdz * invn;

    // view embedding
    if (tid < 27) {
        float val;
        if (tid < 3) {
            val = (tid == 0) ? vx : ((tid == 1) ? vy : vz);
        } else if (tid < 15) {
            int k = tid - 3;
            int d = k >> 2, f = k & 3;
            float v = (d == 0) ? vx : ((d == 1) ? vy : vz);
            val = sinf(v * (float)(1 << f));
        } else {
            int k = tid - 15;
            int d = k >> 2, f = k & 3;
            float v = (d == 0) ? vx : ((d == 1) ? vy : vz);
            val = cosf(v * (float)(1 << f));
        }
        s_vemb[tid] = val;
    }
    if (tid < 3) s_acc[tid] = 0.0f;
    if (tid < 8) s_any[tid] = 0;
    __syncthreads();

    // fold view embedding through w0 (fp32)
    {
        float vw = b0[tid];
        #pragma unroll
        for (int k = 0; k < 27; k++) vw += s_vemb[k] * w0[(12 + k) * 128 + tid];
        s_vw[tid] = vw;
    }

    // ---- alpha for 2 consecutive samples per thread ----------------------
    const float tstep = (TFAR - TNEAR) / 255.0f;
    float a0, a1;
    #pragma unroll
    for (int p = 0; p < 2; p++) {
        int s = 2 * tid + p;
        float t = TNEAR + (float)s * tstep;
        float px = ox + vx * t, py = oy + vy * t, pz = oz + vz * t;
        bool inbox = (px >= -1.0f) & (px <= 1.0f) &
                     (py >= -1.0f) & (py <= 1.0f) &
                     (pz >= -1.0f) & (pz <= 1.0f);
        float alpha = 0.0f;
        if (inbox) {
            int base; float fx, fy, fz;
            tri_setup(px, py, pz, base, fx, fy, fz);
            float d = tri_fetch(dens, base, fx, fy, fz);
            float e = expf(d + ACT_SHIFT);
            alpha = -expm1f(-0.5f * log1pf(e));
        }
        if (p == 0) a0 = alpha; else a1 = alpha;
    }

    // ---- parallel transmittance scan -------------------------------------
    const float m0 = 1.0f - a0, m1 = 1.0f - a1;
    float sc = m0 * m1;
    #pragma unroll
    for (int off = 1; off < 32; off <<= 1) {
        float v = __shfl_up_sync(0xffffffffu, sc, off);
        if (lane >= off) sc *= v;
    }
    float excl = __shfl_up_sync(0xffffffffu, sc, 1);
    if (lane == 0) excl = 1.0f;
    if (lane == 31) s_wtot[wid] = sc;
    __syncthreads();
    {
        float pre = 1.0f;
        #pragma unroll
        for (int w = 0; w < 4; w++) if (w < wid) pre *= s_wtot[w];
        float Te = pre * excl;
        float w0s = a0 * Te;
        float w1s = a1 * Te * m0;
        s_wgt[2 * tid]     = w0s;
        s_wgt[2 * tid + 1] = w1s;
        if ((w0s > WEPS) | (w1s > WEPS)) s_any[tid >> 4] = 1;
        if (tid == 0) s_ainv = s_wtot[0] * s_wtot[1] * s_wtot[2] * s_wtot[3];
    }
    __syncthreads();
    if (tid == 0) {
        int n = 0;
        #pragma unroll
        for (int tl = 0; tl < 8; tl++) if (s_any[tl]) s_list[n++] = tl;
        s_nact = n;
    }

    // ---- resident B fragments (w0, w1) -----------------------------------
    const int nbase = wid * 32;
    unsigned int B1[4][8][2];
    unsigned int B0f[4][2];
    #pragma unroll
    for (int nt = 0; nt < 4; nt++) {
        int n = nbase + nt * 8 + gq;
        #pragma unroll
        for (int ks = 0; ks < 8; ks++) {
            B1[nt][ks][0] = g_w1p[n * 64 + ks * 8 + tq];
            B1[nt][ks][1] = g_w1p[n * 64 + ks * 8 + 4 + tq];
        }
        B0f[nt][0] = g_w0p[n * 8 + tq];
        B0f[nt][1] = g_w0p[n * 8 + 4 + tq];
    }
    float b1lo[4], b1hi[4];
    #pragma unroll
    for (int nt = 0; nt < 4; nt++) {
        int c0 = nbase + nt * 8 + 2 * tq;
        b1lo[nt] = b1[c0];
        b1hi[nt] = b1[c0 + 1];
    }
    const float bias2  = (2 * tq < 3) ? b2[2 * tq] : 0.0f;
    const float bias2b = (2 * tq + 1 < 3) ? b2[2 * tq + 1] : 0.0f;

    // addresses
    const unsigned int xb_base = (unsigned int)__cvta_generic_to_shared(s_xb);
    const unsigned int h0_base = (unsigned int)__cvta_generic_to_shared(s_h0);
    const unsigned int h1_base = (unsigned int)__cvta_generic_to_shared(s_h1);
    const unsigned int cn_base = (unsigned int)__cvta_generic_to_shared(s_corner);
    const int lrow = (((lane >> 3) & 1) << 3) + (lane & 7);
    const int lch  = (lane >> 4) & 1;

    // gather identity: 8 threads per sample
    const int g_css = tid >> 3;
    const int g_c3 = tid & 7;
    const int g_dz = g_c3 & 1;
    const int g_dy = (g_c3 >> 1) & 1;
    const int g_dx = (g_c3 >> 2) & 1;

    float racc0 = 0.0f, racc1 = 0.0f, racc2 = 0.0f, racc3 = 0.0f;

    __syncthreads();
    const int nact = s_nact;

    float cw0, cw1, nw0, nw1;
    if (nact > 0) {
        fetch_tile_async(s_list[0] * 32, g_css, g_c3, g_dx, g_dy, g_dz,
                         ox, oy, oz, vx, vy, vz, tstep, cn_base, cw0, cw1);
        CP_COMMIT();
    }

    for (int i = 0; i < nact; i++) {
        const int s0 = s_list[i] * 32;
        const int buf = i & 1;

        if (i + 1 < nact) {
            fetch_tile_async(s_list[i + 1] * 32, g_css, g_c3, g_dx, g_dy, g_dz,
                             ox, oy, oz, vx, vy, vz, tstep,
                             cn_base + ((i + 1) & 1) * 4096, nw0, nw1);
            CP_COMMIT();
            asm volatile("cp.async.wait_group 1;");
        } else {
            asm volatile("cp.async.wait_group 0;");
        }

        // each thread reduces the records it fetched itself (no barrier needed)
        reduce_store_fp8(&s_corner[buf][g_css * 8 + g_c3],        cw0, g_css,      g_c3, s_xb);
        reduce_store_fp8(&s_corner[buf][(g_css + 16) * 8 + g_c3], cw1, g_css + 16, g_c3, s_xb);
        __syncthreads();

        // ---- layer 0: two m16 halves ----
        #pragma unroll
        for (int mh = 0; mh < 2; mh++) {
            unsigned int a0r, a1r, a2r, a3r;
            LDSM4(a0r, a1r, a2r, a3r, xb_base + (mh * 16 + lrow) * 48 + lch * 16);
            #pragma unroll
            for (int nt = 0; nt < 4; nt++) {
                float C0[4] = {0.0f, 0.0f, 0.0f, 0.0f};
                MMA_BF16(C0, a0r, a1r, a2r, a3r, B0f[nt][0], B0f[nt][1]);
                int cc = nbase + nt * 8 + 2 * tq;
                float v0 = s_vw[cc], v1 = s_vw[cc + 1];
                unsigned int wlo = packbf2(fmaxf(C0[0] + v0, 0.0f),
                                           fmaxf(C0[1] + v1, 0.0f));
                unsigned int whi = packbf2(fmaxf(C0[2] + v0, 0.0f),
                                           fmaxf(C0[3] + v1, 0.0f));
                *reinterpret_cast<unsigned int*>(&s_h0[(mh * 16 + gq) * 136 + cc]) = wlo;
                *reinterpret_cast<unsigned int*>(&s_h0[(mh * 16 + 8 + gq) * 136 + cc]) = whi;
            }
        }
        __syncthreads();

        // ---- layer 1: two m16 halves, B1 register-resident ----
        #pragma unroll
        for (int mh = 0; mh < 2; mh++) {
            float C1[4][4];
            #pragma unroll
            for (int nt = 0; nt < 4; nt++) {
                C1[nt][0] = b1lo[nt]; C1[nt][1] = b1hi[nt];
                C1[nt][2] = b1lo[nt]; C1[nt][3] = b1hi[nt];
            }
            #pragma unroll
            for (int ks = 0; ks < 8; ks++) {
                unsigned int h0r, h1r, h2r, h3r;
                LDSM4(h0r, h1r, h2r, h3r,
                      h0_base + (mh * 16 + lrow) * 272 + ks * 32);
                #pragma unroll
                for (int nt = 0; nt < 4; nt++)
                    MMA_BF16(C1[nt], h0r, h1r, h2r, h3r, B1[nt][ks][0], B1[nt][ks][1]);
            }
            #pragma unroll
            for (int nt = 0; nt < 4; nt++) {
                int cc = nbase + nt * 8 + 2 * tq;
                unsigned int wlo = packbf2(fmaxf(C1[nt][0], 0.0f), fmaxf(C1[nt][1], 0.0f));
                unsigned int whi = packbf2(fmaxf(C1[nt][2], 0.0f), fmaxf(C1[nt][3], 0.0f));
                *reinterpret_cast<unsigned int*>(&s_h1[(mh * 16 + gq) * 136 + cc]) = wlo;
                *reinterpret_cast<unsigned int*>(&s_h1[(mh * 16 + 8 + gq) * 136 + cc]) = whi;
            }
        }
        __syncthreads();

        // ---- layer 2: warps 0,1 take one m16 half each ----
        if (wid < 2) {
            const int mh = wid;
            float C2[4] = {bias2, bias2b, bias2, bias2b};
            #pragma unroll
            for (int ks = 0; ks < 8; ks++) {
                unsigned int h0r, h1r, h2r, h3r;
                LDSM4(h0r, h1r, h2r, h3r,
                      h1_base + (mh * 16 + lrow) * 272 + ks * 32);
                unsigned int wb0 = g_w2p[gq * 64 + ks * 8 + tq];
                unsigned int wb1 = g_w2p[gq * 64 + ks * 8 + 4 + tq];
                MMA_BF16(C2, h0r, h1r, h2r, h3r, wb0, wb1);
            }
            float wlo = s_wgt[s0 + mh * 16 + gq];
            float whi = s_wgt[s0 + mh * 16 + 8 + gq];
            int col0 = 2 * tq;
            if (col0 < 3) {
                racc0 += wlo * sigm(C2[0]);
                racc2 += whi * sigm(C2[2]);
            }
            if (col0 + 1 < 3) {
                racc1 += wlo * sigm(C2[1]);
                racc3 += whi * sigm(C2[3]);
            }
        }

        cw0 = nw0; cw1 = nw1;
    }

    if (wid < 2) {
        int col0 = 2 * tq;
        if (col0 < 3)     atomicAdd(&s_acc[col0],     racc0 + racc2);
        if (col0 + 1 < 3) atomicAdd(&s_acc[col0 + 1], racc1 + racc3);
    }
    __syncthreads();
    if (tid < 3) out[ray * 3 + tid] = s_acc[tid] + s_ainv;
}

extern "C" void kernel_launch(void* const* d_in, const int* in_sizes, int n_in,
                              void* d_out, int out_size)
{
    const float* rays_o = (const float*)d_in[0];
    const float* rays_d = (const float*)d_in[1];
    const float* dens   = (const float*)d_in[2];
    const float* feat   = (const float*)d_in[3];
    const float* w0     = (const float*)d_in[4];
    const float* b0     = (const float*)d_in[5];
    const float* w1     = (const float*)d_in[6];
    const float* b1     = (const float*)d_in[7];
    const float* w2     = (const float*)d_in[8];
    const float* b2     = (const float*)d_in[9];
    float* out = (float*)d_out;

    prep_kernel<<<32, 256>>>(w0, w1, w2);
    relayout_kernel<<<RES3 / 256, 256>>>(feat);
    dvgo_kernel<<<NRAYS, 128>>>(rays_o, rays_d, dens, feat,
                                w0, b0, w1, b1, w2, b2, out);
}

// round 14
// speedup vs baseline: 6.2785x; 1.0517x over previous
#include <cuda_runtime.h>
#include <cuda_bf16.h>
#include <cuda_fp16.h>
#include <cuda_fp8.h>
#include <math.h>

#define NRAYS 4096
#define NS    256
#define RES   160
#define RES2  (RES*RES)
#define RES3  (RES*RES*RES)
#define TNEAR 0.05f
#define TFAR  2.0f
#define ACT_SHIFT (-13.8155095579f)
#define WEPS  1e-9f

// packed bf16x2 weight fragments: [n][kpair], low half = even k
__device__ unsigned int g_w0p[128 * 8];    // layer0 (feature part / 16)
__device__ unsigned int g_w1p[128 * 64];   // layer1
__device__ unsigned int g_w2p[8 * 64];     // layer2

// fp8 channel-interleaved feature grid: 16B record = 12 e4m3 (x16 scaled) + 4 pad
__device__ __align__(16) unsigned int g_pack[RES3 * 4];   // 65.5 MB

__device__ __forceinline__ unsigned int packbf2(float lo, float hi) {
    __nv_bfloat162 h = __floats2bfloat162_rn(lo, hi);
    return *reinterpret_cast<unsigned int*>(&h);
}

__global__ void prep_kernel(const float* __restrict__ w0,
                            const float* __restrict__ w1,
                            const float* __restrict__ w2)
{
    int i = blockIdx.x * 256 + threadIdx.x;
    if (i < 128 * 64) {
        int n = i >> 6, p = i & 63;
        g_w1p[i] = packbf2(w1[(2 * p) * 128 + n], w1[(2 * p + 1) * 128 + n]);
    }
    if (i < 128 * 8) {             // w0 feature rows carry the 1/16 descale
        int n = i >> 3, p = i & 7;
        int k0 = 2 * p, k1 = 2 * p + 1;
        float lo = (k0 < 12) ? w0[k0 * 128 + n] * 0.0625f : 0.0f;
        float hi = (k1 < 12) ? w0[k1 * 128 + n] * 0.0625f : 0.0f;
        g_w0p[i] = packbf2(lo, hi);
    }
    if (i < 8 * 64) {
        int n = i >> 6, p = i & 63;
        float lo = (n < 3) ? w2[(2 * p) * 3 + n] : 0.0f;
        float hi = (n < 3) ? w2[(2 * p + 1) * 3 + n] : 0.0f;
        g_w2p[i] = packbf2(lo, hi);
    }
}

// [12][RES3] fp32 -> [RES3] 16B fp8 records (value*16, e4m3)
__global__ void relayout_kernel(const float* __restrict__ feat)
{
    int v = blockIdx.x * 256 + threadIdx.x;
    if (v >= RES3) return;
    unsigned int r[3];
    #pragma unroll
    for (int p = 0; p < 3; p++) {
        unsigned int w = 0;
        #pragma unroll
        for (int j = 0; j < 4; j++) {
            int c = 4 * p + j;
            unsigned int b = (unsigned int)__nv_cvt_float_to_fp8(
                feat[c * RES3 + v] * 16.0f, __NV_SATFINITE, __NV_E4M3);
            w |= b << (8 * j);
        }
        r[p] = w;
    }
    reinterpret_cast<uint4*>(g_pack)[v] = make_uint4(r[0], r[1], r[2], 0u);
}

#define LDSM4(A0,A1,A2,A3,addr) \
    asm volatile("ldmatrix.sync.aligned.m8n8.x4.shared.b16 {%0,%1,%2,%3}, [%4];" \
        : "=r"(A0), "=r"(A1), "=r"(A2), "=r"(A3) : "r"(addr))

#define MMA_BF16(C,A0,A1,A2,A3,B0r,B1r) \
    asm volatile("mma.sync.aligned.m16n8k16.row.col.f32.bf16.bf16.f32 " \
        "{%0,%1,%2,%3}, {%4,%5,%6,%7}, {%8,%9}, {%0,%1,%2,%3};" \
        : "+f"((C)[0]), "+f"((C)[1]), "+f"((C)[2]), "+f"((C)[3]) \
        : "r"(A0), "r"(A1), "r"(A2), "r"(A3), "r"(B0r), "r"(B1r))

#define CP_ASYNC16(dst, src) \
    asm volatile("cp.async.cg.shared.global [%0], [%1], 16;" \
        :: "r"(dst), "l"(src))
#define CP_COMMIT() asm volatile("cp.async.commit_group;")

__device__ __forceinline__ void tri_setup(float px, float py, float pz,
                                          int& base, float& fx, float& fy, float& fz)
{
    float ix = fminf(fmaxf((px + 1.0f) * 79.5f, 0.0f), 159.0f);
    float iy = fminf(fmaxf((py + 1.0f) * 79.5f, 0.0f), 159.0f);
    float iz = fminf(fmaxf((pz + 1.0f) * 79.5f, 0.0f), 159.0f);
    int x0 = min((int)ix, 158);
    int y0 = min((int)iy, 158);
    int z0 = min((int)iz, 158);
    fx = ix - (float)x0;
    fy = iy - (float)y0;
    fz = iz - (float)z0;
    base = x0 * RES2 + y0 * RES + z0;
}

__device__ __forceinline__ float tri_fetch(const float* __restrict__ g, int base,
                                           float fx, float fy, float fz)
{
    float c000 = g[base];
    float c001 = g[base + 1];
    float c010 = g[base + RES];
    float c011 = g[base + RES + 1];
    const float* g1 = g + base + RES2;
    float c100 = g1[0];
    float c101 = g1[1];
    float c110 = g1[RES];
    float c111 = g1[RES + 1];
    float gz = 1.0f - fz;
    float c00 = c000 * gz + c001 * fz;
    float c01 = c010 * gz + c011 * fz;
    float c10 = c100 * gz + c101 * fz;
    float c11 = c110 * gz + c111 * fz;
    float gy = 1.0f - fy;
    float c0 = c00 * gy + c01 * fy;
    float c1 = c10 * gy + c11 * fy;
    return c0 * (1.0f - fx) + c1 * fx;
}

__device__ __forceinline__ float sigm(float x) { return 1.0f / (1.0f + __expf(-x)); }

// issue cp.async for the two corner records of this thread for one tile
__device__ __forceinline__ void fetch_tile_async(
    int s0, int css, int c3, int dx, int dy, int dz,
    float ox, float oy, float oz, float vx, float vy, float vz, float tstep,
    unsigned int cbuf, float& w0v, float& w1v)
{
    #pragma unroll
    for (int p = 0; p < 2; p++) {
        int ss = css + p * 16;
        float t = TNEAR + (float)(s0 + ss) * tstep;
        float px = ox + vx * t, py = oy + vy * t, pz = oz + vz * t;
        int base; float fx, fy, fz;
        tri_setup(px, py, pz, base, fx, fy, fz);
        float w = (dx ? fx : 1.0f - fx) * (dy ? fy : 1.0f - fy) * (dz ? fz : 1.0f - fz);
        const unsigned int* src = g_pack +
            (size_t)(base + dx * RES2 + dy * RES + dz) * 4;
        unsigned int dst = cbuf + (unsigned int)(ss * 8 + c3) * 16;
        CP_ASYNC16(dst, src);
        if (p == 0) w0v = w; else w1v = w;
    }
}

// half2 weighted shfl-reduce over 8 corner lanes; lane c3==0 stores sample row
__device__ __forceinline__ void reduce_store_h2(
    const uint4* rec_p, float w, int row, int c3, __nv_bfloat16* s_xb)
{
    uint4 rec = *rec_p;
    unsigned int wd[3] = {rec.x, rec.y, rec.z};
    __half2 h[6];
    #pragma unroll
    for (int p = 0; p < 3; p++) {
        __half2_raw lo = __nv_cvt_fp8x2_to_halfraw2(
            (__nv_fp8x2_storage_t)(wd[p] & 0xFFFFu), __NV_E4M3);
        __half2_raw hi = __nv_cvt_fp8x2_to_halfraw2(
            (__nv_fp8x2_storage_t)(wd[p] >> 16), __NV_E4M3);
        h[2 * p]     = *reinterpret_cast<__half2*>(&lo);
        h[2 * p + 1] = *reinterpret_cast<__half2*>(&hi);
    }
    __half2 wh = __float2half2_rn(w);
    #pragma unroll
    for (int j = 0; j < 6; j++) h[j] = __hmul2(h[j], wh);
    #pragma unroll
    for (int r = 4; r >= 1; r >>= 1) {
        #pragma unroll
        for (int j = 0; j < 6; j++) {
            unsigned int v = __shfl_xor_sync(0xffffffffu,
                *reinterpret_cast<unsigned int*>(&h[j]), r);
            h[j] = __hadd2(h[j], *reinterpret_cast<__half2*>(&v));
        }
    }
    if (c3 == 0) {
        unsigned int o[8];
        #pragma unroll
        for (int j = 0; j < 6; j++) {
            float2 f2 = __half22float2(h[j]);
            o[j] = packbf2(f2.x, f2.y);
        }
        o[6] = 0u; o[7] = 0u;
        uint4* dst = reinterpret_cast<uint4*>(&s_xb[row * 24]);
        dst[0] = make_uint4(o[0], o[1], o[2], o[3]);
        dst[1] = make_uint4(o[4], o[5], o[6], o[7]);
    }
}

// --- main fused kernel: one block (128 threads) per ray --------------------
__global__ __launch_bounds__(128, 4)
void dvgo_kernel(const float* __restrict__ rays_o, const float* __restrict__ rays_d,
                 const float* __restrict__ dens,  const float* __restrict__ feat,
                 const float* __restrict__ w0,    const float* __restrict__ b0,
                 const float* __restrict__ w1,    const float* __restrict__ b1,
                 const float* __restrict__ w2,    const float* __restrict__ b2,
                 float* __restrict__ out)
{
    __shared__ __align__(16) __nv_bfloat16 s_h0[32 * 136];
    __shared__ __align__(16) __nv_bfloat16 s_xb[32 * 24];
    __shared__ __align__(16) uint4 s_corner[2][256];   // 2 x 4KB fp8 records
    __shared__ float s_rgb[96];                         // 32 samples x 3 (pre-sigmoid)
    __shared__ float s_vw[128];
    __shared__ float s_vemb[27];
    __shared__ float s_wgt[NS];
    __shared__ float s_wtot[4];
    __shared__ int   s_any[8];
    __shared__ int   s_list[8];
    __shared__ int   s_nact;
    __shared__ float s_acc[3];
    __shared__ float s_ainv;

    const int ray = blockIdx.x;
    const int tid = threadIdx.x;
    const int wid = tid >> 5;
    const int lane = tid & 31;
    const int gq = lane >> 2;
    const int tq = lane & 3;

    const float ox = rays_o[ray * 3 + 0];
    const float oy = rays_o[ray * 3 + 1];
    const float oz = rays_o[ray * 3 + 2];
    float rdx = rays_d[ray * 3 + 0];
    float rdy = rays_d[ray * 3 + 1];
    float rdz = rays_d[ray * 3 + 2];
    const float invn = rsqrtf(rdx * rdx + rdy * rdy + rdz * rdz);
    const float vx = rdx * invn, vy = rdy * invn, vz = rdz * invn;

    // view embedding
    if (tid < 27) {
        float val;
        if (tid < 3) {
            val = (tid == 0) ? vx : ((tid == 1) ? vy : vz);
        } else if (tid < 15) {
            int k = tid - 3;
            int d = k >> 2, f = k & 3;
            float v = (d == 0) ? vx : ((d == 1) ? vy : vz);
            val = sinf(v * (float)(1 << f));
        } else {
            int k = tid - 15;
            int d = k >> 2, f = k & 3;
            float v = (d == 0) ? vx : ((d == 1) ? vy : vz);
            val = cosf(v * (float)(1 << f));
        }
        s_vemb[tid] = val;
    }
    if (tid < 3) s_acc[tid] = 0.0f;
    if (tid < 8) s_any[tid] = 0;
    __syncthreads();

    // fold view embedding through w0 (fp32)
    {
        float vw = b0[tid];
        #pragma unroll
        for (int k = 0; k < 27; k++) vw += s_vemb[k] * w0[(12 + k) * 128 + tid];
        s_vw[tid] = vw;
    }

    // ---- alpha for 2 consecutive samples per thread ----------------------
    const float tstep = (TFAR - TNEAR) / 255.0f;
    float a0, a1;
    #pragma unroll
    for (int p = 0; p < 2; p++) {
        int s = 2 * tid + p;
        float t = TNEAR + (float)s * tstep;
        float px = ox + vx * t, py = oy + vy * t, pz = oz + vz * t;
        bool inbox = (px >= -1.0f) & (px <= 1.0f) &
                     (py >= -1.0f) & (py <= 1.0f) &
                     (pz >= -1.0f) & (pz <= 1.0f);
        float alpha = 0.0f;
        if (inbox) {
            int base; float fx, fy, fz;
            tri_setup(px, py, pz, base, fx, fy, fz);
            float d = tri_fetch(dens, base, fx, fy, fz);
            float e = expf(d + ACT_SHIFT);
            alpha = -expm1f(-0.5f * log1pf(e));
        }
        if (p == 0) a0 = alpha; else a1 = alpha;
    }

    // ---- parallel transmittance scan -------------------------------------
    const float m0 = 1.0f - a0, m1 = 1.0f - a1;
    float sc = m0 * m1;
    #pragma unroll
    for (int off = 1; off < 32; off <<= 1) {
        float v = __shfl_up_sync(0xffffffffu, sc, off);
        if (lane >= off) sc *= v;
    }
    float excl = __shfl_up_sync(0xffffffffu, sc, 1);
    if (lane == 0) excl = 1.0f;
    if (lane == 31) s_wtot[wid] = sc;
    __syncthreads();
    {
        float pre = 1.0f;
        #pragma unroll
        for (int w = 0; w < 4; w++) if (w < wid) pre *= s_wtot[w];
        float Te = pre * excl;
        float w0s = a0 * Te;
        float w1s = a1 * Te * m0;
        s_wgt[2 * tid]     = w0s;
        s_wgt[2 * tid + 1] = w1s;
        if ((w0s > WEPS) | (w1s > WEPS)) s_any[tid >> 4] = 1;
        if (tid == 0) s_ainv = s_wtot[0] * s_wtot[1] * s_wtot[2] * s_wtot[3];
    }
    __syncthreads();
    if (tid == 0) {
        int n = 0;
        #pragma unroll
        for (int tl = 0; tl < 8; tl++) if (s_any[tl]) s_list[n++] = tl;
        s_nact = n;
    }

    // ---- resident B fragments (w0, w1, w2) -------------------------------
    const int nbase = wid * 32;
    unsigned int B1[4][8][2];
    unsigned int B0f[4][2];
    #pragma unroll
    for (int nt = 0; nt < 4; nt++) {
        int n = nbase + nt * 8 + gq;
        #pragma unroll
        for (int ks = 0; ks < 8; ks++) {
            B1[nt][ks][0] = g_w1p[n * 64 + ks * 8 + tq];
            B1[nt][ks][1] = g_w1p[n * 64 + ks * 8 + 4 + tq];
        }
        B0f[nt][0] = g_w0p[n * 8 + tq];
        B0f[nt][1] = g_w0p[n * 8 + 4 + tq];
    }
    float b1lo[4], b1hi[4];
    #pragma unroll
    for (int nt = 0; nt < 4; nt++) {
        int c0 = nbase + nt * 8 + 2 * tq;
        b1lo[nt] = b1[c0];
        b1hi[nt] = b1[c0 + 1];
    }
    // w2 B-fragments for this warp's two k-blocks (ks = wid*2 + j)
    unsigned int W2[2][2];
    #pragma unroll
    for (int j = 0; j < 2; j++) {
        W2[j][0] = g_w2p[gq * 64 + (wid * 2 + j) * 8 + tq];
        W2[j][1] = g_w2p[gq * 64 + (wid * 2 + j) * 8 + 4 + tq];
    }
    const float biasr = (tid < 96) ? b2[tid % 3] : 0.0f;

    // addresses
    const unsigned int xb_base = (unsigned int)__cvta_generic_to_shared(s_xb);
    const unsigned int h0_base = (unsigned int)__cvta_generic_to_shared(s_h0);
    const unsigned int cn_base = (unsigned int)__cvta_generic_to_shared(s_corner);
    const int lrow = (((lane >> 3) & 1) << 3) + (lane & 7);
    const int lch  = (lane >> 4) & 1;

    // gather identity: 8 threads per sample
    const int g_css = tid >> 3;
    const int g_c3 = tid & 7;
    const int g_dz = g_c3 & 1;
    const int g_dy = (g_c3 >> 1) & 1;
    const int g_dx = (g_c3 >> 2) & 1;

    float racc = 0.0f;   // per-thread (sample tid/3, channel tid%3) accumulator

    __syncthreads();
    const int nact = s_nact;

    float cw0, cw1, nw0, nw1;
    if (nact > 0) {
        fetch_tile_async(s_list[0] * 32, g_css, g_c3, g_dx, g_dy, g_dz,
                         ox, oy, oz, vx, vy, vz, tstep, cn_base, cw0, cw1);
        CP_COMMIT();
    }

    for (int i = 0; i < nact; i++) {
        const int s0 = s_list[i] * 32;
        const int buf = i & 1;

        if (i + 1 < nact) {
            fetch_tile_async(s_list[i + 1] * 32, g_css, g_c3, g_dx, g_dy, g_dz,
                             ox, oy, oz, vx, vy, vz, tstep,
                             cn_base + ((i + 1) & 1) * 4096, nw0, nw1);
            CP_COMMIT();
            asm volatile("cp.async.wait_group 1;");
        } else {
            asm volatile("cp.async.wait_group 0;");
        }

        // each thread reduces the records it fetched itself
        reduce_store_h2(&s_corner[buf][g_css * 8 + g_c3],        cw0, g_css,      g_c3, s_xb);
        reduce_store_h2(&s_corner[buf][(g_css + 16) * 8 + g_c3], cw1, g_css + 16, g_c3, s_xb);
        __syncthreads();                                   // barrier A

        // interval A->B: seed rgb accumulator with bias; layer 0
        if (tid < 96) s_rgb[tid] = biasr;
        #pragma unroll
        for (int mh = 0; mh < 2; mh++) {
            unsigned int a0r, a1r, a2r, a3r;
            LDSM4(a0r, a1r, a2r, a3r, xb_base + (mh * 16 + lrow) * 48 + lch * 16);
            #pragma unroll
            for (int nt = 0; nt < 4; nt++) {
                float C0[4] = {0.0f, 0.0f, 0.0f, 0.0f};
                MMA_BF16(C0, a0r, a1r, a2r, a3r, B0f[nt][0], B0f[nt][1]);
                int cc = nbase + nt * 8 + 2 * tq;
                float v0 = s_vw[cc], v1 = s_vw[cc + 1];
                unsigned int wlo = packbf2(fmaxf(C0[0] + v0, 0.0f),
                                           fmaxf(C0[1] + v1, 0.0f));
                unsigned int whi = packbf2(fmaxf(C0[2] + v0, 0.0f),
                                           fmaxf(C0[3] + v1, 0.0f));
                *reinterpret_cast<unsigned int*>(&s_h0[(mh * 16 + gq) * 136 + cc]) = wlo;
                *reinterpret_cast<unsigned int*>(&s_h0[(mh * 16 + 8 + gq) * 136 + cc]) = whi;
            }
        }
        __syncthreads();                                   // barrier B

        // interval B->C: layer 1 (B1 resident) + layer 2 partial from registers
        #pragma unroll
        for (int mh = 0; mh < 2; mh++) {
            float C1[4][4];
            #pragma unroll
            for (int nt = 0; nt < 4; nt++) {
                C1[nt][0] = b1lo[nt]; C1[nt][1] = b1hi[nt];
                C1[nt][2] = b1lo[nt]; C1[nt][3] = b1hi[nt];
            }
            #pragma unroll
            for (int ks = 0; ks < 8; ks++) {
                unsigned int h0r, h1r, h2r, h3r;
                LDSM4(h0r, h1r, h2r, h3r,
                      h0_base + (mh * 16 + lrow) * 272 + ks * 32);
                #pragma unroll
                for (int nt = 0; nt < 4; nt++)
                    MMA_BF16(C1[nt], h0r, h1r, h2r, h3r, B1[nt][ks][0], B1[nt][ks][1]);
            }
            // relu + repack C1 directly as layer-2 A fragments (no smem trip)
            float C2[4] = {0.0f, 0.0f, 0.0f, 0.0f};
            #pragma unroll
            for (int j = 0; j < 2; j++) {
                unsigned int a0p = packbf2(fmaxf(C1[2*j][0], 0.0f), fmaxf(C1[2*j][1], 0.0f));
                unsigned int a1p = packbf2(fmaxf(C1[2*j][2], 0.0f), fmaxf(C1[2*j][3], 0.0f));
                unsigned int a2p = packbf2(fmaxf(C1[2*j+1][0], 0.0f), fmaxf(C1[2*j+1][1], 0.0f));
                unsigned int a3p = packbf2(fmaxf(C1[2*j+1][2], 0.0f), fmaxf(C1[2*j+1][3], 0.0f));
                MMA_BF16(C2, a0p, a1p, a2p, a3p, W2[j][0], W2[j][1]);
            }
            // combine partials across warps (pre-sigmoid)
            int r0 = (mh * 16 + gq) * 3, r1 = (mh * 16 + 8 + gq) * 3;
            int c0 = 2 * tq;
            if (c0 < 3) {
                atomicAdd(&s_rgb[r0 + c0], C2[0]);
                atomicAdd(&s_rgb[r1 + c0], C2[2]);
            }
            if (c0 + 1 < 3) {
                atomicAdd(&s_rgb[r0 + c0 + 1], C2[1]);
                atomicAdd(&s_rgb[r1 + c0 + 1], C2[3]);
            }
        }
        __syncthreads();                                   // barrier C

        // sigmoid + weighted accumulate (96 threads: sample tid/3, ch tid%3)
        if (tid < 96) racc += s_wgt[s0 + tid / 3] * sigm(s_rgb[tid]);

        cw0 = nw0; cw1 = nw1;
    }

    if (tid < 96) atomicAdd(&s_acc[tid % 3], racc);
    __syncthreads();
    if (tid < 3) out[ray * 3 + tid] = s_acc[tid] + s_ainv;
}

extern "C" void kernel_launch(void* const* d_in, const int* in_sizes, int n_in,
                              void* d_out, int out_size)
{
    const float* rays_o = (const float*)d_in[0];
    const float* rays_d = (const float*)d_in[1];
    const float* dens   = (const float*)d_in[2];
    const float* feat   = (const float*)d_in[3];
    const float* w0     = (const float*)d_in[4];
    const float* b0     = (const float*)d_in[5];
    const float* w1     = (const float*)d_in[6];
    const float* b1     = (const float*)d_in[7];
    const float* w2     = (const float*)d_in[8];
    const float* b2     = (const float*)d_in[9];
    float* out = (float*)d_out;

    prep_kernel<<<32, 256>>>(w0, w1, w2);
    relayout_kernel<<<RES3 / 256, 256>>>(feat);
    dvgo_kernel<<<NRAYS, 128>>>(rays_o, rays_d, dens, feat,
                                w0, b0, w1, b1, w2, b2, out);
}